// round 2
// baseline (speedup 1.0000x reference)
#include <cuda_runtime.h>
#include <cuda_bf16.h>
#include <math.h>

#define BB 2
#define LL 2048
#define CC 1024
#define HH 16
#define DD 64
#define ML (BB*LL)   /* 4096 rows */

// ---------------- scratch (device globals: allocation-guard-legal) ----------
__device__ float g_qh[BB*HH*LL*DD];   // [B,H,L,D] 16 MB
__device__ float g_kh[BB*HH*LL*DD];
__device__ float g_vh[BB*HH*LL*DD];
__device__ float g_ctx[BB*LL*CC];     // attention output, [B,L,C]
__device__ float g_bias[BB*LL];       // 0 or -1e30 per (b, key_pos)
__device__ int   g_maskfmt;           // 0=int32, 1=float32, 2=bytes(bool)

// ---------------- mask dtype detection -------------------------------------
__global__ void detect_mask_kernel(const unsigned int* __restrict__ m) {
    __shared__ int s_i32, s_f32;
    if (threadIdx.x == 0) { s_i32 = 1; s_f32 = 1; }
    __syncthreads();
    int i32 = 1, f32 = 1;
    for (int i = threadIdx.x; i < 1024; i += 256) {   // 4 KB: in-bounds for all layouts
        unsigned v = m[i];
        if (v > 1u) i32 = 0;
        if (v != 0u && v != 0x3F800000u) f32 = 0;
    }
    if (!i32) atomicAnd(&s_i32, 0);
    if (!f32) atomicAnd(&s_f32, 0);
    __syncthreads();
    if (threadIdx.x == 0) g_maskfmt = s_i32 ? 0 : (s_f32 ? 1 : 2);
}

__global__ void fill_bias_kernel(const void* __restrict__ mp) {
    int i = blockIdx.x * 256 + threadIdx.x;
    if (i >= BB*LL) return;
    int fmt = g_maskfmt;
    bool on;
    if (fmt == 0)      on = ((const int*)mp)[i] != 0;
    else if (fmt == 1) on = ((const float*)mp)[i] != 0.0f;
    else               on = ((const unsigned char*)mp)[i] != 0;
    g_bias[i] = on ? 0.0f : -1e30f;
}

// ---------------- NT GEMM: out[m,n] = sum_k A[m,k] * W[n,k]  ----------------
// mode 0: write head layout [B,H,L,D];  mode 1: plain [M,N] + bias[n]
__global__ __launch_bounds__(256)
void gemm_nt_kernel(const float* __restrict__ A, const float* __restrict__ W,
                    float* __restrict__ out, const float* __restrict__ bias, int mode)
{
    __shared__ float As[16][64];   // As[k][m]
    __shared__ float Bs[16][64];   // Bs[k][n]
    const int bm = blockIdx.y * 64;
    const int bn = blockIdx.x * 64;
    const int tid = threadIdx.x;
    const int ty = tid >> 4, tx = tid & 15;
    const int lr = tid >> 2;              // 0..63
    const int lk = (tid & 3) << 2;        // 0,4,8,12

    float acc[4][4];
#pragma unroll
    for (int i = 0; i < 4; i++)
#pragma unroll
        for (int j = 0; j < 4; j++) acc[i][j] = 0.0f;

    const float* Arow = A + (size_t)(bm + lr) * CC;
    const float* Wrow = W + (size_t)(bn + lr) * CC;

    for (int k0 = 0; k0 < CC; k0 += 16) {
        float4 av = *(const float4*)(Arow + k0 + lk);
        float4 wv = *(const float4*)(Wrow + k0 + lk);
        As[lk+0][lr] = av.x; As[lk+1][lr] = av.y; As[lk+2][lr] = av.z; As[lk+3][lr] = av.w;
        Bs[lk+0][lr] = wv.x; Bs[lk+1][lr] = wv.y; Bs[lk+2][lr] = wv.z; Bs[lk+3][lr] = wv.w;
        __syncthreads();
#pragma unroll
        for (int k = 0; k < 16; k++) {
            float4 a = *(const float4*)&As[k][ty << 2];
            float4 b = *(const float4*)&Bs[k][tx << 2];
            acc[0][0] += a.x*b.x; acc[0][1] += a.x*b.y; acc[0][2] += a.x*b.z; acc[0][3] += a.x*b.w;
            acc[1][0] += a.y*b.x; acc[1][1] += a.y*b.y; acc[1][2] += a.y*b.z; acc[1][3] += a.y*b.w;
            acc[2][0] += a.z*b.x; acc[2][1] += a.z*b.y; acc[2][2] += a.z*b.z; acc[2][3] += a.z*b.w;
            acc[3][0] += a.w*b.x; acc[3][1] += a.w*b.y; acc[3][2] += a.w*b.z; acc[3][3] += a.w*b.w;
        }
        __syncthreads();
    }

    if (mode == 0) {
        const int h = bn >> 6;             // whole block maps to one head
#pragma unroll
        for (int i = 0; i < 4; i++) {
            int m = bm + (ty << 2) + i;
            int b = m >> 11;               // m = b*L + l
            int l = m & (LL - 1);
            float4 o = make_float4(acc[i][0], acc[i][1], acc[i][2], acc[i][3]);
            *(float4*)&out[(((size_t)b * HH + h) * LL + l) * DD + (tx << 2)] = o;
        }
    } else {
        int n = bn + (tx << 2);
        float4 bv = *(const float4*)&bias[n];
#pragma unroll
        for (int i = 0; i < 4; i++) {
            int m = bm + (ty << 2) + i;
            float4 o = make_float4(acc[i][0] + bv.x, acc[i][1] + bv.y,
                                   acc[i][2] + bv.z, acc[i][3] + bv.w);
            *(float4*)&out[(size_t)m * CC + n] = o;
        }
    }
}

// ---------------- RoPE (in-place on g_qh, g_kh) -----------------------------
__global__ void rope_kernel() {
    int gid = blockIdx.x * 256 + threadIdx.x;
    if (gid >= BB*HH*LL*32) return;
    int d   = gid & 31;
    int row = gid >> 5;                  // (b*H+h)*L + l
    int l   = row & (LL - 1);
    // ln(50000) = 10.819778284410283
    double inv = exp(-10.819778284410283 * (double)(2 * d) / 64.0);
    double f = (double)l * inv;
    double sn, cs;
    sincos(f, &sn, &cs);
    float c = (float)cs, s = (float)sn;
    float* qp = g_qh + (size_t)row * DD;
    float* kp = g_kh + (size_t)row * DD;
    float a = qp[d], b2 = qp[d + 32];
    qp[d]      = a  * c - b2 * s;
    qp[d + 32] = b2 * c + a  * s;
    float ak = kp[d], bk = kp[d + 32];
    kp[d]      = ak * c - bk * s;
    kp[d + 32] = bk * c + ak * s;
}

// ---------------- Flash attention (fp32, online softmax) --------------------
// grid: (L/64 q-tiles, B*H).  block: 256 threads, 4x4 micro tiles.
#define SMS 68   /* padded smem row stride */
__global__ __launch_bounds__(256)
void flash_kernel()
{
    extern __shared__ float sm[];
    float* Qt = sm;                 // [64][SMS]  Qt[d][r]
    float* Kt = sm + 64 * SMS;      // Kt[d][c]
    float* Vs = sm + 2 * 64 * SMS;  // Vs[s][c]
    float* Pt = sm + 3 * 64 * SMS;  // Pt[s][r]
    float* biasS = sm + 4 * 64 * SMS;  // [64]

    const int q0 = blockIdx.x * 64;
    const int bh = blockIdx.y;
    const int b  = bh >> 4;
    const int h  = bh & 15;
    const int tid = threadIdx.x;
    const int ty = tid >> 4, tx = tid & 15;
    const int lr = tid >> 2, lk = (tid & 3) << 2;

    const float* qbase = g_qh + (size_t)bh * LL * DD;
    const float* kbase = g_kh + (size_t)bh * LL * DD;
    const float* vbase = g_vh + (size_t)bh * LL * DD;

    // Q tile -> transposed smem: full 64x64 tile (4 chunks of 16 dims each)
#pragma unroll
    for (int kk = 0; kk < 64; kk += 16) {
        float4 v = *(const float4*)&qbase[(size_t)(q0 + lr) * DD + kk + lk];
        Qt[(kk+lk+0)*SMS + lr] = v.x; Qt[(kk+lk+1)*SMS + lr] = v.y;
        Qt[(kk+lk+2)*SMS + lr] = v.z; Qt[(kk+lk+3)*SMS + lr] = v.w;
    }

    float O[4][4];
    float m[4], l[4];
#pragma unroll
    for (int i = 0; i < 4; i++) {
        m[i] = -1e30f; l[i] = 0.0f;
#pragma unroll
        for (int j = 0; j < 4; j++) O[i][j] = 0.0f;
    }

    for (int s0 = 0; s0 < LL; s0 += 64) {
        // load K (transposed), V (natural), bias — full 64x64 tiles
#pragma unroll
        for (int kk = 0; kk < 64; kk += 16) {
            float4 kv = *(const float4*)&kbase[(size_t)(s0 + lr) * DD + kk + lk];
            Kt[(kk+lk+0)*SMS + lr] = kv.x; Kt[(kk+lk+1)*SMS + lr] = kv.y;
            Kt[(kk+lk+2)*SMS + lr] = kv.z; Kt[(kk+lk+3)*SMS + lr] = kv.w;
            float4 vv = *(const float4*)&vbase[(size_t)(s0 + lr) * DD + kk + lk];
            *(float4*)&Vs[lr * SMS + kk + lk] = vv;
        }
        if (tid < 64) biasS[tid] = g_bias[b * LL + s0 + tid];
        __syncthreads();

        // GEMM1: S = Q K^T
        float S[4][4];
#pragma unroll
        for (int i = 0; i < 4; i++)
#pragma unroll
            for (int j = 0; j < 4; j++) S[i][j] = 0.0f;
#pragma unroll 16
        for (int d = 0; d < 64; d++) {
            float4 a = *(const float4*)&Qt[d * SMS + (ty << 2)];
            float4 kb = *(const float4*)&Kt[d * SMS + (tx << 2)];
            S[0][0] += a.x*kb.x; S[0][1] += a.x*kb.y; S[0][2] += a.x*kb.z; S[0][3] += a.x*kb.w;
            S[1][0] += a.y*kb.x; S[1][1] += a.y*kb.y; S[1][2] += a.y*kb.z; S[1][3] += a.y*kb.w;
            S[2][0] += a.z*kb.x; S[2][1] += a.z*kb.y; S[2][2] += a.z*kb.z; S[2][3] += a.z*kb.w;
            S[3][0] += a.w*kb.x; S[3][1] += a.w*kb.y; S[3][2] += a.w*kb.z; S[3][3] += a.w*kb.w;
        }

        float bj0 = biasS[(tx<<2)+0], bj1 = biasS[(tx<<2)+1];
        float bj2 = biasS[(tx<<2)+2], bj3 = biasS[(tx<<2)+3];

        // online softmax (row reductions over the 16 tx lanes of each ty group)
#pragma unroll
        for (int i = 0; i < 4; i++) {
            S[i][0] = S[i][0]*0.125f + bj0;
            S[i][1] = S[i][1]*0.125f + bj1;
            S[i][2] = S[i][2]*0.125f + bj2;
            S[i][3] = S[i][3]*0.125f + bj3;
            float rm = fmaxf(fmaxf(S[i][0], S[i][1]), fmaxf(S[i][2], S[i][3]));
#pragma unroll
            for (int off = 1; off < 16; off <<= 1)
                rm = fmaxf(rm, __shfl_xor_sync(0xffffffffu, rm, off));
            float mn = fmaxf(m[i], rm);
            float sc = __expf(m[i] - mn);
            float rs = 0.0f;
#pragma unroll
            for (int j = 0; j < 4; j++) {
                float p = __expf(S[i][j] - mn);
                S[i][j] = p;
                rs += p;
            }
#pragma unroll
            for (int off = 1; off < 16; off <<= 1)
                rs += __shfl_xor_sync(0xffffffffu, rs, off);
            l[i] = l[i] * sc + rs;
            m[i] = mn;
#pragma unroll
            for (int j = 0; j < 4; j++) O[i][j] *= sc;
        }

        // stage P transposed
#pragma unroll
        for (int j = 0; j < 4; j++)
#pragma unroll
            for (int i = 0; i < 4; i++)
                Pt[((tx<<2)+j) * SMS + (ty<<2) + i] = S[i][j];
        __syncthreads();

        // GEMM2: O += P V
#pragma unroll 16
        for (int s = 0; s < 64; s++) {
            float4 p = *(const float4*)&Pt[s * SMS + (ty << 2)];
            float4 v = *(const float4*)&Vs[s * SMS + (tx << 2)];
            O[0][0] += p.x*v.x; O[0][1] += p.x*v.y; O[0][2] += p.x*v.z; O[0][3] += p.x*v.w;
            O[1][0] += p.y*v.x; O[1][1] += p.y*v.y; O[1][2] += p.y*v.z; O[1][3] += p.y*v.w;
            O[2][0] += p.z*v.x; O[2][1] += p.z*v.y; O[2][2] += p.z*v.z; O[2][3] += p.z*v.w;
            O[3][0] += p.w*v.x; O[3][1] += p.w*v.y; O[3][2] += p.w*v.z; O[3][3] += p.w*v.w;
        }
        __syncthreads();
    }

    // normalize + write ctx [B,L,C]
#pragma unroll
    for (int i = 0; i < 4; i++) {
        float inv = 1.0f / l[i];
        int row = q0 + (ty << 2) + i;
        float4 o = make_float4(O[i][0]*inv, O[i][1]*inv, O[i][2]*inv, O[i][3]*inv);
        *(float4*)&g_ctx[((size_t)b * LL + row) * CC + h * DD + (tx << 2)] = o;
    }
}

// ---------------- launch -----------------------------------------------------
extern "C" void kernel_launch(void* const* d_in, const int* in_sizes, int n_in,
                              void* d_out, int out_size)
{
    const float* q  = (const float*)d_in[0];
    const void*  mk = d_in[1];
    const float* Wq = (const float*)d_in[2];
    const float* Wk = (const float*)d_in[3];
    const float* Wv = (const float*)d_in[4];
    const float* Wo = (const float*)d_in[5];
    const float* bo = (const float*)d_in[6];
    float* out = (float*)d_out;

    float *qh, *kh, *vh, *ctx;
    cudaGetSymbolAddress((void**)&qh,  g_qh);
    cudaGetSymbolAddress((void**)&kh,  g_kh);
    cudaGetSymbolAddress((void**)&vh,  g_vh);
    cudaGetSymbolAddress((void**)&ctx, g_ctx);

    const int smemB = (4 * 64 * SMS + 64) * (int)sizeof(float);
    cudaFuncSetAttribute(flash_kernel, cudaFuncAttributeMaxDynamicSharedMemorySize, smemB);

    detect_mask_kernel<<<1, 256>>>((const unsigned int*)mk);
    fill_bias_kernel<<<(BB*LL + 255) / 256, 256>>>(mk);

    dim3 gg(CC / 64, ML / 64);   // (16, 64)
    gemm_nt_kernel<<<gg, 256>>>(q, Wq, qh, nullptr, 0);
    gemm_nt_kernel<<<gg, 256>>>(q, Wk, kh, nullptr, 0);
    gemm_nt_kernel<<<gg, 256>>>(q, Wv, vh, nullptr, 0);

    int ropeN = BB * HH * LL * 32;
    rope_kernel<<<(ropeN + 255) / 256, 256>>>();

    dim3 gf(LL / 64, BB * HH);   // (32, 32)
    flash_kernel<<<gf, 256, smemB>>>();

    gemm_nt_kernel<<<gg, 256>>>(ctx, Wo, out, bo, 1);
}

// round 3
// speedup vs baseline: 1.0398x; 1.0398x over previous
#include <cuda_runtime.h>
#include <cuda_bf16.h>
#include <math.h>

#define BB 2
#define LL 2048
#define CC 1024
#define HH 16
#define DD 64
#define ML (BB*LL)

// ---------------- scratch (device globals) ----------------------------------
__device__ float g_qh[BB*HH*LL*DD];   // [B,H,L,D]
__device__ float g_kh[BB*HH*LL*DD];
__device__ float g_vh[BB*HH*LL*DD];
__device__ float g_ctx[BB*LL*CC];     // [B,L,C]
__device__ float g_bias[BB*LL];
__device__ int   g_maskfmt;

// ---------------- mask handling ---------------------------------------------
__global__ void detect_mask_kernel(const unsigned int* __restrict__ m) {
    __shared__ int s_i32, s_f32;
    if (threadIdx.x == 0) { s_i32 = 1; s_f32 = 1; }
    __syncthreads();
    int i32 = 1, f32 = 1;
    for (int i = threadIdx.x; i < 1024; i += 256) {
        unsigned v = m[i];
        if (v > 1u) i32 = 0;
        if (v != 0u && v != 0x3F800000u) f32 = 0;
    }
    if (!i32) atomicAnd(&s_i32, 0);
    if (!f32) atomicAnd(&s_f32, 0);
    __syncthreads();
    if (threadIdx.x == 0) g_maskfmt = s_i32 ? 0 : (s_f32 ? 1 : 2);
}

__global__ void fill_bias_kernel(const void* __restrict__ mp) {
    int i = blockIdx.x * 256 + threadIdx.x;
    if (i >= BB*LL) return;
    int fmt = g_maskfmt;
    bool on;
    if (fmt == 0)      on = ((const int*)mp)[i] != 0;
    else if (fmt == 1) on = ((const float*)mp)[i] != 0.0f;
    else               on = ((const unsigned char*)mp)[i] != 0;
    g_bias[i] = on ? 0.0f : -1e30f;
}

// ---------------- 128x128 NT GEMM core (8x8 microtiles) ---------------------
// acc[m][n] = sum_k A[bm+m, k] * W[bn+n, k]
__device__ __forceinline__ void gemm_tile(const float* __restrict__ A,
                                          const float* __restrict__ W,
                                          int bm, int bn, float acc[8][8],
                                          float (*As)[128], float (*Bs)[128])
{
    const int tid  = threadIdx.x;
    const int r    = tid & 127;
    const int half = tid >> 7;           // 0/1 -> k-offset half*8
    const int ty   = tid >> 4;
    const int tx   = tid & 15;

    const float* Ap = A + (size_t)(bm + r) * CC + half * 8;
    const float* Wp = W + (size_t)(bn + r) * CC + half * 8;

#pragma unroll
    for (int i = 0; i < 8; i++)
#pragma unroll
        for (int j = 0; j < 8; j++) acc[i][j] = 0.0f;

    // first tile
    {
        float4 a0 = *(const float4*)(Ap);
        float4 a1 = *(const float4*)(Ap + 4);
        float4 b0 = *(const float4*)(Wp);
        float4 b1 = *(const float4*)(Wp + 4);
        As[half*8+0][r]=a0.x; As[half*8+1][r]=a0.y; As[half*8+2][r]=a0.z; As[half*8+3][r]=a0.w;
        As[half*8+4][r]=a1.x; As[half*8+5][r]=a1.y; As[half*8+6][r]=a1.z; As[half*8+7][r]=a1.w;
        Bs[half*8+0][r]=b0.x; Bs[half*8+1][r]=b0.y; Bs[half*8+2][r]=b0.z; Bs[half*8+3][r]=b0.w;
        Bs[half*8+4][r]=b1.x; Bs[half*8+5][r]=b1.y; Bs[half*8+6][r]=b1.z; Bs[half*8+7][r]=b1.w;
    }
    __syncthreads();

    int kb = 0;   // current buffer base row (0 or 16)
    for (int k0 = 16; k0 < CC; k0 += 16) {
        float4 a0 = *(const float4*)(Ap + k0);
        float4 a1 = *(const float4*)(Ap + k0 + 4);
        float4 b0 = *(const float4*)(Wp + k0);
        float4 b1 = *(const float4*)(Wp + k0 + 4);

#pragma unroll
        for (int kk = 0; kk < 16; kk++) {
            float4 x0 = *(const float4*)&As[kb+kk][ty*8];
            float4 x1 = *(const float4*)&As[kb+kk][ty*8+4];
            float4 y0 = *(const float4*)&Bs[kb+kk][tx*8];
            float4 y1 = *(const float4*)&Bs[kb+kk][tx*8+4];
            float xa[8] = {x0.x,x0.y,x0.z,x0.w,x1.x,x1.y,x1.z,x1.w};
            float yb[8] = {y0.x,y0.y,y0.z,y0.w,y1.x,y1.y,y1.z,y1.w};
#pragma unroll
            for (int i = 0; i < 8; i++)
#pragma unroll
                for (int j = 0; j < 8; j++) acc[i][j] += xa[i]*yb[j];
        }

        int nb = kb ^ 16;
        As[nb+half*8+0][r]=a0.x; As[nb+half*8+1][r]=a0.y; As[nb+half*8+2][r]=a0.z; As[nb+half*8+3][r]=a0.w;
        As[nb+half*8+4][r]=a1.x; As[nb+half*8+5][r]=a1.y; As[nb+half*8+6][r]=a1.z; As[nb+half*8+7][r]=a1.w;
        Bs[nb+half*8+0][r]=b0.x; Bs[nb+half*8+1][r]=b0.y; Bs[nb+half*8+2][r]=b0.z; Bs[nb+half*8+3][r]=b0.w;
        Bs[nb+half*8+4][r]=b1.x; Bs[nb+half*8+5][r]=b1.y; Bs[nb+half*8+6][r]=b1.z; Bs[nb+half*8+7][r]=b1.w;
        __syncthreads();
        kb = nb;
    }
    // last tile
#pragma unroll
    for (int kk = 0; kk < 16; kk++) {
        float4 x0 = *(const float4*)&As[kb+kk][ty*8];
        float4 x1 = *(const float4*)&As[kb+kk][ty*8+4];
        float4 y0 = *(const float4*)&Bs[kb+kk][tx*8];
        float4 y1 = *(const float4*)&Bs[kb+kk][tx*8+4];
        float xa[8] = {x0.x,x0.y,x0.z,x0.w,x1.x,x1.y,x1.z,x1.w};
        float yb[8] = {y0.x,y0.y,y0.z,y0.w,y1.x,y1.y,y1.z,y1.w};
#pragma unroll
        for (int i = 0; i < 8; i++)
#pragma unroll
            for (int j = 0; j < 8; j++) acc[i][j] += xa[i]*yb[j];
    }
}

// QKV fused: grid (8, 32, 3)
__global__ __launch_bounds__(256)
void qkv_kernel(const float* __restrict__ A, const float* __restrict__ Wq,
                const float* __restrict__ Wk, const float* __restrict__ Wv)
{
    __shared__ float As[32][128];
    __shared__ float Bs[32][128];
    const float* W = (blockIdx.z == 0) ? Wq : (blockIdx.z == 1 ? Wk : Wv);
    float* out = (blockIdx.z == 0) ? g_qh : (blockIdx.z == 1 ? g_kh : g_vh);
    const int bm = blockIdx.y * 128, bn = blockIdx.x * 128;

    float acc[8][8];
    gemm_tile(A, W, bm, bn, acc, As, Bs);

    const int tid = threadIdx.x, ty = tid >> 4, tx = tid & 15;
    const int h    = (bn >> 6) + (tx >> 3);
    const int colh = (tx & 7) * 8;
#pragma unroll
    for (int i = 0; i < 8; i++) {
        int mrow = bm + ty*8 + i;
        int b = mrow >> 11, l = mrow & (LL - 1);
        float* dst = out + (((size_t)b * HH + h) * LL + l) * DD + colh;
        *(float4*)dst       = make_float4(acc[i][0], acc[i][1], acc[i][2], acc[i][3]);
        *(float4*)(dst + 4) = make_float4(acc[i][4], acc[i][5], acc[i][6], acc[i][7]);
    }
}

// output projection + bias: grid (8, 32)
__global__ __launch_bounds__(256)
void oproj_kernel(const float* __restrict__ A, const float* __restrict__ Wo,
                  const float* __restrict__ bo, float* __restrict__ out)
{
    __shared__ float As[32][128];
    __shared__ float Bs[32][128];
    const int bm = blockIdx.y * 128, bn = blockIdx.x * 128;

    float acc[8][8];
    gemm_tile(A, Wo, bm, bn, acc, As, Bs);

    const int tid = threadIdx.x, ty = tid >> 4, tx = tid & 15;
    const int n = bn + tx * 8;
    float4 bv0 = *(const float4*)&bo[n];
    float4 bv1 = *(const float4*)&bo[n + 4];
#pragma unroll
    for (int i = 0; i < 8; i++) {
        int mrow = bm + ty*8 + i;
        float* dst = out + (size_t)mrow * CC + n;
        *(float4*)dst       = make_float4(acc[i][0]+bv0.x, acc[i][1]+bv0.y, acc[i][2]+bv0.z, acc[i][3]+bv0.w);
        *(float4*)(dst + 4) = make_float4(acc[i][4]+bv1.x, acc[i][5]+bv1.y, acc[i][6]+bv1.z, acc[i][7]+bv1.w);
    }
}

// ---------------- RoPE ------------------------------------------------------
__global__ void rope_kernel() {
    int gid = blockIdx.x * 256 + threadIdx.x;
    if (gid >= BB*HH*LL*32) return;
    int d   = gid & 31;
    int row = gid >> 5;
    int l   = row & (LL - 1);
    double inv = exp(-10.819778284410283 * (double)(2 * d) / 64.0);  // ln(50000)
    double f = (double)l * inv;
    double sn, cs;
    sincos(f, &sn, &cs);
    float c = (float)cs, s = (float)sn;
    float* qp = g_qh + (size_t)row * DD;
    float* kp = g_kh + (size_t)row * DD;
    float a = qp[d], b2 = qp[d + 32];
    qp[d]      = a  * c - b2 * s;
    qp[d + 32] = b2 * c + a  * s;
    float ak = kp[d], bk = kp[d + 32];
    kp[d]      = ak * c - bk * s;
    kp[d + 32] = bk * c + ak * s;
}

// ---------------- Flash attention: 128 q-rows x 64-key tiles, 8x4 micro ----
#define QT_S 132
#define KT_S 68
#define VS_S 68
#define PS_S 68
#define OFF_KT 8448      /* 64*132 */
#define OFF_VS 12800     /* +64*68 */
#define OFF_PS 17152     /* +64*68 */
#define OFF_BI 25856     /* +128*68 */
#define FLASH_SMEM_FLOATS 25920

__global__ __launch_bounds__(256)
void flash_kernel()
{
    extern __shared__ float smf[];
    float* Qt = smf;             // Qt[d][r]
    float* Kt = smf + OFF_KT;    // Kt[d][c]
    float* Vs = smf + OFF_VS;    // Vs[s][c]
    float* Ps = smf + OFF_PS;    // Ps[r][s]
    float* biasS = smf + OFF_BI;

    const int q0 = blockIdx.x * 128;
    const int bh = blockIdx.y;
    const int b  = bh >> 4;
    const int h  = bh & 15;
    const int tid = threadIdx.x;
    const int ty = tid >> 4, tx = tid & 15;

    const float* qbase = g_qh + (size_t)bh * LL * DD;
    const float* kbase = g_kh + (size_t)bh * LL * DD;
    const float* vbase = g_vh + (size_t)bh * LL * DD;

    // Q tile 128x64 -> transposed smem
    {
        const int r = tid & 127, hf = tid >> 7;   // 2 threads/row, 32 dims each
        const float* qp = qbase + (size_t)(q0 + r) * DD + hf * 32;
#pragma unroll
        for (int j = 0; j < 8; j++) {
            float4 v = *(const float4*)(qp + j * 4);
            int d0 = hf * 32 + j * 4;
            Qt[(d0+0)*QT_S + r] = v.x; Qt[(d0+1)*QT_S + r] = v.y;
            Qt[(d0+2)*QT_S + r] = v.z; Qt[(d0+3)*QT_S + r] = v.w;
        }
    }

    float O[8][4];
    float m[8], l[8];
#pragma unroll
    for (int i = 0; i < 8; i++) {
        m[i] = -1e30f; l[i] = 0.0f;
#pragma unroll
        for (int j = 0; j < 4; j++) O[i][j] = 0.0f;
    }

    const int c64 = tid & 63, dh = tid >> 6;   // 4 quarters of 16 dims

    for (int s0 = 0; s0 < LL; s0 += 64) {
        // K transposed, V natural
        {
            const float* kp = kbase + (size_t)(s0 + c64) * DD + dh * 16;
            const float* vp = vbase + (size_t)(s0 + c64) * DD + dh * 16;
#pragma unroll
            for (int j = 0; j < 4; j++) {
                float4 kv = *(const float4*)(kp + j * 4);
                int d0 = dh * 16 + j * 4;
                Kt[(d0+0)*KT_S + c64] = kv.x; Kt[(d0+1)*KT_S + c64] = kv.y;
                Kt[(d0+2)*KT_S + c64] = kv.z; Kt[(d0+3)*KT_S + c64] = kv.w;
                float4 vv = *(const float4*)(vp + j * 4);
                *(float4*)&Vs[c64 * VS_S + d0] = vv;
            }
            if (tid < 64) biasS[tid] = g_bias[b * LL + s0 + tid];
        }
        __syncthreads();

        // GEMM1: S[128x64] = Q K^T
        float S[8][4];
#pragma unroll
        for (int i = 0; i < 8; i++)
#pragma unroll
            for (int j = 0; j < 4; j++) S[i][j] = 0.0f;
#pragma unroll 8
        for (int d = 0; d < 64; d++) {
            float4 a0 = *(const float4*)&Qt[d*QT_S + ty*8];
            float4 a1 = *(const float4*)&Qt[d*QT_S + ty*8 + 4];
            float4 kf = *(const float4*)&Kt[d*KT_S + tx*4];
            float qa[8] = {a0.x,a0.y,a0.z,a0.w,a1.x,a1.y,a1.z,a1.w};
#pragma unroll
            for (int i = 0; i < 8; i++) {
                S[i][0] += qa[i]*kf.x; S[i][1] += qa[i]*kf.y;
                S[i][2] += qa[i]*kf.z; S[i][3] += qa[i]*kf.w;
            }
        }

        float bj0 = biasS[tx*4+0], bj1 = biasS[tx*4+1];
        float bj2 = biasS[tx*4+2], bj3 = biasS[tx*4+3];

        // online softmax, rows reduced over 16 tx lanes
#pragma unroll
        for (int i = 0; i < 8; i++) {
            S[i][0] = S[i][0]*0.125f + bj0;
            S[i][1] = S[i][1]*0.125f + bj1;
            S[i][2] = S[i][2]*0.125f + bj2;
            S[i][3] = S[i][3]*0.125f + bj3;
            float rm = fmaxf(fmaxf(S[i][0], S[i][1]), fmaxf(S[i][2], S[i][3]));
#pragma unroll
            for (int off = 1; off < 16; off <<= 1)
                rm = fmaxf(rm, __shfl_xor_sync(0xffffffffu, rm, off));
            float mn = fmaxf(m[i], rm);
            float sc = __expf(m[i] - mn);
            float rs = 0.0f;
#pragma unroll
            for (int j = 0; j < 4; j++) {
                float p = __expf(S[i][j] - mn);
                S[i][j] = p;
                rs += p;
            }
#pragma unroll
            for (int off = 1; off < 16; off <<= 1)
                rs += __shfl_xor_sync(0xffffffffu, rs, off);
            l[i] = l[i] * sc + rs;
            m[i] = mn;
#pragma unroll
            for (int j = 0; j < 4; j++) O[i][j] *= sc;
        }

        // store P naturally (rows are warp-private)
#pragma unroll
        for (int i = 0; i < 8; i++)
            *(float4*)&Ps[(ty*8+i)*PS_S + tx*4] =
                make_float4(S[i][0], S[i][1], S[i][2], S[i][3]);
        __syncwarp();

        // GEMM2: O += P V
#pragma unroll 4
        for (int sc4 = 0; sc4 < 64; sc4 += 4) {
            float4 v0 = *(const float4*)&Vs[(sc4+0)*VS_S + tx*4];
            float4 v1 = *(const float4*)&Vs[(sc4+1)*VS_S + tx*4];
            float4 v2 = *(const float4*)&Vs[(sc4+2)*VS_S + tx*4];
            float4 v3 = *(const float4*)&Vs[(sc4+3)*VS_S + tx*4];
#pragma unroll
            for (int i = 0; i < 8; i++) {
                float4 p = *(const float4*)&Ps[(ty*8+i)*PS_S + sc4];
                O[i][0] += p.x*v0.x + p.y*v1.x + p.z*v2.x + p.w*v3.x;
                O[i][1] += p.x*v0.y + p.y*v1.y + p.z*v2.y + p.w*v3.y;
                O[i][2] += p.x*v0.z + p.y*v1.z + p.z*v2.z + p.w*v3.z;
                O[i][3] += p.x*v0.w + p.y*v1.w + p.z*v2.w + p.w*v3.w;
            }
        }
        __syncthreads();
    }

    // normalize + write ctx [B,L,C]
#pragma unroll
    for (int i = 0; i < 8; i++) {
        float inv = 1.0f / l[i];
        int row = q0 + ty*8 + i;
        float4 o = make_float4(O[i][0]*inv, O[i][1]*inv, O[i][2]*inv, O[i][3]*inv);
        *(float4*)&g_ctx[((size_t)b * LL + row) * CC + h * DD + tx*4] = o;
    }
}

// ---------------- launch -----------------------------------------------------
extern "C" void kernel_launch(void* const* d_in, const int* in_sizes, int n_in,
                              void* d_out, int out_size)
{
    const float* q  = (const float*)d_in[0];
    const void*  mk = d_in[1];
    const float* Wq = (const float*)d_in[2];
    const float* Wk = (const float*)d_in[3];
    const float* Wv = (const float*)d_in[4];
    const float* Wo = (const float*)d_in[5];
    const float* bo = (const float*)d_in[6];
    float* out = (float*)d_out;

    float* ctx;
    cudaGetSymbolAddress((void**)&ctx, g_ctx);

    const int smemB = FLASH_SMEM_FLOATS * (int)sizeof(float);
    cudaFuncSetAttribute(flash_kernel, cudaFuncAttributeMaxDynamicSharedMemorySize, smemB);

    detect_mask_kernel<<<1, 256>>>((const unsigned int*)mk);
    fill_bias_kernel<<<(BB*LL + 255) / 256, 256>>>(mk);

    qkv_kernel<<<dim3(CC/128, ML/128, 3), 256>>>(q, Wq, Wk, Wv);

    int ropeN = BB * HH * LL * 32;
    rope_kernel<<<(ropeN + 255) / 256, 256>>>();

    flash_kernel<<<dim3(LL/128, BB*HH), 256, smemB>>>();

    oproj_kernel<<<dim3(CC/128, ML/128), 256>>>(ctx, Wo, bo, out);
}

// round 4
// speedup vs baseline: 1.1504x; 1.1063x over previous
#include <cuda_runtime.h>
#include <cuda_bf16.h>
#include <math.h>

#define BB 2
#define LL 2048
#define CC 1024
#define HH 16
#define DD 64
#define ML (BB*LL)

typedef unsigned long long u64t;

// ---------------- f32x2 packed helpers (Blackwell FFMA2 path) ---------------
__device__ __forceinline__ u64t f2pk(float lo, float hi) {
    u64t r; asm("mov.b64 %0, {%1, %2};" : "=l"(r) : "f"(lo), "f"(hi)); return r;
}
__device__ __forceinline__ u64t ffma2(u64t a, u64t b, u64t c) {
    u64t d; asm("fma.rn.f32x2 %0, %1, %2, %3;" : "=l"(d) : "l"(a), "l"(b), "l"(c)); return d;
}
__device__ __forceinline__ u64t fmul2(u64t a, u64t b) {
    u64t d; asm("mul.rn.f32x2 %0, %1, %2;" : "=l"(d) : "l"(a), "l"(b)); return d;
}
__device__ __forceinline__ float2 f2up(u64t v) {
    float2 f; asm("mov.b64 {%0, %1}, %2;" : "=f"(f.x), "=f"(f.y) : "l"(v)); return f;
}

// ---------------- scratch ----------------------------------------------------
__device__ float g_qh[BB*HH*LL*DD];
__device__ float g_kh[BB*HH*LL*DD];
__device__ float g_vh[BB*HH*LL*DD];
__device__ float g_ctx[BB*LL*CC];
__device__ float g_bias[BB*LL];
__device__ float2 g_ropeTab[LL*32];
__device__ int   g_maskfmt;

// ---------------- mask handling ---------------------------------------------
__global__ void detect_mask_kernel(const unsigned int* __restrict__ m) {
    __shared__ int s_i32, s_f32;
    if (threadIdx.x == 0) { s_i32 = 1; s_f32 = 1; }
    __syncthreads();
    int i32 = 1, f32 = 1;
    for (int i = threadIdx.x; i < 1024; i += 256) {
        unsigned v = m[i];
        if (v > 1u) i32 = 0;
        if (v != 0u && v != 0x3F800000u) f32 = 0;
    }
    if (!i32) atomicAnd(&s_i32, 0);
    if (!f32) atomicAnd(&s_f32, 0);
    __syncthreads();
    if (threadIdx.x == 0) g_maskfmt = s_i32 ? 0 : (s_f32 ? 1 : 2);
}

__global__ void fill_bias_kernel(const void* __restrict__ mp) {
    int i = blockIdx.x * 256 + threadIdx.x;
    if (i >= BB*LL) return;
    int fmt = g_maskfmt;
    bool on;
    if (fmt == 0)      on = ((const int*)mp)[i] != 0;
    else if (fmt == 1) on = ((const float*)mp)[i] != 0.0f;
    else               on = ((const unsigned char*)mp)[i] != 0;
    g_bias[i] = on ? 0.0f : -1e30f;
}

// ---------------- RoPE: tiny table build (double precision) + cheap apply ---
__global__ void rope_table_kernel() {
    int gid = blockIdx.x * 256 + threadIdx.x;
    if (gid >= LL*32) return;
    int d = gid & 31, l = gid >> 5;
    double inv = exp(-10.819778284410283 * (double)(2 * d) / 64.0);  // ln(50000)
    double sn, cs;
    sincos((double)l * inv, &sn, &cs);
    g_ropeTab[gid] = make_float2((float)cs, (float)sn);
}

__global__ void rope_apply_kernel() {
    int gid = blockIdx.x * 256 + threadIdx.x;
    if (gid >= BB*HH*LL*32) return;
    int d   = gid & 31;
    int row = gid >> 5;
    int l   = row & (LL - 1);
    float2 cs = g_ropeTab[l * 32 + d];
    float c = cs.x, s = cs.y;
    float* qp = g_qh + (size_t)row * DD;
    float* kp = g_kh + (size_t)row * DD;
    float a = qp[d], b2 = qp[d + 32];
    qp[d]      = a  * c - b2 * s;
    qp[d + 32] = b2 * c + a  * s;
    float ak = kp[d], bk = kp[d + 32];
    kp[d]      = ak * c - bk * s;
    kp[d + 32] = bk * c + ak * s;
}

// ---------------- 128x128 NT GEMM core, f32x2 accumulators ------------------
__device__ __forceinline__ void gemm_tile(const float* __restrict__ A,
                                          const float* __restrict__ W,
                                          int bm, int bn, u64t acc2[8][4],
                                          float (*As)[128], float (*Bs)[128])
{
    const int tid  = threadIdx.x;
    const int r    = tid & 127;
    const int half = tid >> 7;
    const int ty   = tid >> 4;
    const int tx   = tid & 15;

    const float* Ap = A + (size_t)(bm + r) * CC + half * 8;
    const float* Wp = W + (size_t)(bn + r) * CC + half * 8;

#pragma unroll
    for (int i = 0; i < 8; i++)
#pragma unroll
        for (int j = 0; j < 4; j++) acc2[i][j] = 0ULL;

    {
        float4 a0 = *(const float4*)(Ap);
        float4 a1 = *(const float4*)(Ap + 4);
        float4 b0 = *(const float4*)(Wp);
        float4 b1 = *(const float4*)(Wp + 4);
        As[half*8+0][r]=a0.x; As[half*8+1][r]=a0.y; As[half*8+2][r]=a0.z; As[half*8+3][r]=a0.w;
        As[half*8+4][r]=a1.x; As[half*8+5][r]=a1.y; As[half*8+6][r]=a1.z; As[half*8+7][r]=a1.w;
        Bs[half*8+0][r]=b0.x; Bs[half*8+1][r]=b0.y; Bs[half*8+2][r]=b0.z; Bs[half*8+3][r]=b0.w;
        Bs[half*8+4][r]=b1.x; Bs[half*8+5][r]=b1.y; Bs[half*8+6][r]=b1.z; Bs[half*8+7][r]=b1.w;
    }
    __syncthreads();

    int kb = 0;
    for (int k0 = 16; k0 < CC; k0 += 16) {
        float4 a0 = *(const float4*)(Ap + k0);
        float4 a1 = *(const float4*)(Ap + k0 + 4);
        float4 b0 = *(const float4*)(Wp + k0);
        float4 b1 = *(const float4*)(Wp + k0 + 4);

#pragma unroll
        for (int kk = 0; kk < 16; kk++) {
            float4 x0 = *(const float4*)&As[kb+kk][ty*8];
            float4 x1 = *(const float4*)&As[kb+kk][ty*8+4];
            float4 y0 = *(const float4*)&Bs[kb+kk][tx*8];
            float4 y1 = *(const float4*)&Bs[kb+kk][tx*8+4];
            u64t yp[4] = { f2pk(y0.x,y0.y), f2pk(y0.z,y0.w),
                           f2pk(y1.x,y1.y), f2pk(y1.z,y1.w) };
            float xa[8] = {x0.x,x0.y,x0.z,x0.w,x1.x,x1.y,x1.z,x1.w};
#pragma unroll
            for (int i = 0; i < 8; i++) {
                u64t xb = f2pk(xa[i], xa[i]);
#pragma unroll
                for (int j = 0; j < 4; j++)
                    acc2[i][j] = ffma2(xb, yp[j], acc2[i][j]);
            }
        }

        int nb = kb ^ 16;
        As[nb+half*8+0][r]=a0.x; As[nb+half*8+1][r]=a0.y; As[nb+half*8+2][r]=a0.z; As[nb+half*8+3][r]=a0.w;
        As[nb+half*8+4][r]=a1.x; As[nb+half*8+5][r]=a1.y; As[nb+half*8+6][r]=a1.z; As[nb+half*8+7][r]=a1.w;
        Bs[nb+half*8+0][r]=b0.x; Bs[nb+half*8+1][r]=b0.y; Bs[nb+half*8+2][r]=b0.z; Bs[nb+half*8+3][r]=b0.w;
        Bs[nb+half*8+4][r]=b1.x; Bs[nb+half*8+5][r]=b1.y; Bs[nb+half*8+6][r]=b1.z; Bs[nb+half*8+7][r]=b1.w;
        __syncthreads();
        kb = nb;
    }
#pragma unroll
    for (int kk = 0; kk < 16; kk++) {
        float4 x0 = *(const float4*)&As[kb+kk][ty*8];
        float4 x1 = *(const float4*)&As[kb+kk][ty*8+4];
        float4 y0 = *(const float4*)&Bs[kb+kk][tx*8];
        float4 y1 = *(const float4*)&Bs[kb+kk][tx*8+4];
        u64t yp[4] = { f2pk(y0.x,y0.y), f2pk(y0.z,y0.w),
                       f2pk(y1.x,y1.y), f2pk(y1.z,y1.w) };
        float xa[8] = {x0.x,x0.y,x0.z,x0.w,x1.x,x1.y,x1.z,x1.w};
#pragma unroll
        for (int i = 0; i < 8; i++) {
            u64t xb = f2pk(xa[i], xa[i]);
#pragma unroll
            for (int j = 0; j < 4; j++)
                acc2[i][j] = ffma2(xb, yp[j], acc2[i][j]);
        }
    }
}

// QKV fused: grid (8, 32, 3)
__global__ __launch_bounds__(256)
void qkv_kernel(const float* __restrict__ A, const float* __restrict__ Wq,
                const float* __restrict__ Wk, const float* __restrict__ Wv)
{
    __shared__ float As[32][128];
    __shared__ float Bs[32][128];
    const float* W = (blockIdx.z == 0) ? Wq : (blockIdx.z == 1 ? Wk : Wv);
    float* out = (blockIdx.z == 0) ? g_qh : (blockIdx.z == 1 ? g_kh : g_vh);
    const int bm = blockIdx.y * 128, bn = blockIdx.x * 128;

    u64t acc2[8][4];
    gemm_tile(A, W, bm, bn, acc2, As, Bs);

    const int tid = threadIdx.x, ty = tid >> 4, tx = tid & 15;
    const int h    = (bn >> 6) + (tx >> 3);
    const int colh = (tx & 7) * 8;
#pragma unroll
    for (int i = 0; i < 8; i++) {
        int mrow = bm + ty*8 + i;
        int b = mrow >> 11, l = mrow & (LL - 1);
        float* dst = out + (((size_t)b * HH + h) * LL + l) * DD + colh;
        float2 p0 = f2up(acc2[i][0]), p1 = f2up(acc2[i][1]);
        float2 p2 = f2up(acc2[i][2]), p3 = f2up(acc2[i][3]);
        *(float4*)dst       = make_float4(p0.x, p0.y, p1.x, p1.y);
        *(float4*)(dst + 4) = make_float4(p2.x, p2.y, p3.x, p3.y);
    }
}

// output projection + bias: grid (8, 32)
__global__ __launch_bounds__(256)
void oproj_kernel(const float* __restrict__ A, const float* __restrict__ Wo,
                  const float* __restrict__ bo, float* __restrict__ out)
{
    __shared__ float As[32][128];
    __shared__ float Bs[32][128];
    const int bm = blockIdx.y * 128, bn = blockIdx.x * 128;

    u64t acc2[8][4];
    gemm_tile(A, Wo, bm, bn, acc2, As, Bs);

    const int tid = threadIdx.x, ty = tid >> 4, tx = tid & 15;
    const int n = bn + tx * 8;
    float4 bv0 = *(const float4*)&bo[n];
    float4 bv1 = *(const float4*)&bo[n + 4];
#pragma unroll
    for (int i = 0; i < 8; i++) {
        int mrow = bm + ty*8 + i;
        float* dst = out + (size_t)mrow * CC + n;
        float2 p0 = f2up(acc2[i][0]), p1 = f2up(acc2[i][1]);
        float2 p2 = f2up(acc2[i][2]), p3 = f2up(acc2[i][3]);
        *(float4*)dst       = make_float4(p0.x+bv0.x, p0.y+bv0.y, p1.x+bv0.z, p1.y+bv0.w);
        *(float4*)(dst + 4) = make_float4(p2.x+bv1.x, p2.y+bv1.y, p3.x+bv1.z, p3.y+bv1.w);
    }
}

// ---------------- Flash attention: 128x64 tiles, f32x2 math -----------------
#define QT_S 132
#define KT_S 68
#define VS_S 68
#define PS_S 68
#define OFF_KT 8448
#define OFF_VS 12800
#define OFF_PS 17152
#define OFF_BI 25856
#define FLASH_SMEM_FLOATS 25920

__global__ __launch_bounds__(256)
void flash_kernel()
{
    extern __shared__ float smf[];
    float* Qt = smf;
    float* Kt = smf + OFF_KT;
    float* Vs = smf + OFF_VS;
    float* Ps = smf + OFF_PS;
    float* biasS = smf + OFF_BI;

    const int q0 = blockIdx.x * 128;
    const int bh = blockIdx.y;
    const int b  = bh >> 4;
    const int h  = bh & 15;
    const int tid = threadIdx.x;
    const int ty = tid >> 4, tx = tid & 15;

    const float* qbase = g_qh + (size_t)bh * LL * DD;
    const float* kbase = g_kh + (size_t)bh * LL * DD;
    const float* vbase = g_vh + (size_t)bh * LL * DD;

    {
        const int r = tid & 127, hf = tid >> 7;
        const float* qp = qbase + (size_t)(q0 + r) * DD + hf * 32;
#pragma unroll
        for (int j = 0; j < 8; j++) {
            float4 v = *(const float4*)(qp + j * 4);
            int d0 = hf * 32 + j * 4;
            Qt[(d0+0)*QT_S + r] = v.x; Qt[(d0+1)*QT_S + r] = v.y;
            Qt[(d0+2)*QT_S + r] = v.z; Qt[(d0+3)*QT_S + r] = v.w;
        }
    }

    u64t O2[8][2];
    float m[8], l[8];
#pragma unroll
    for (int i = 0; i < 8; i++) {
        m[i] = -1e30f; l[i] = 0.0f;
        O2[i][0] = 0ULL; O2[i][1] = 0ULL;
    }

    const int c64 = tid & 63, dh = tid >> 6;

    for (int s0 = 0; s0 < LL; s0 += 64) {
        {
            const float* kp = kbase + (size_t)(s0 + c64) * DD + dh * 16;
            const float* vp = vbase + (size_t)(s0 + c64) * DD + dh * 16;
#pragma unroll
            for (int j = 0; j < 4; j++) {
                float4 kv = *(const float4*)(kp + j * 4);
                int d0 = dh * 16 + j * 4;
                Kt[(d0+0)*KT_S + c64] = kv.x; Kt[(d0+1)*KT_S + c64] = kv.y;
                Kt[(d0+2)*KT_S + c64] = kv.z; Kt[(d0+3)*KT_S + c64] = kv.w;
                float4 vv = *(const float4*)(vp + j * 4);
                *(float4*)&Vs[c64 * VS_S + d0] = vv;
            }
            if (tid < 64) biasS[tid] = g_bias[b * LL + s0 + tid];
        }
        __syncthreads();

        // GEMM1: S = Q K^T (packed pairs along key columns)
        u64t S2[8][2];
#pragma unroll
        for (int i = 0; i < 8; i++) { S2[i][0] = 0ULL; S2[i][1] = 0ULL; }
#pragma unroll 8
        for (int d = 0; d < 64; d++) {
            float4 a0 = *(const float4*)&Qt[d*QT_S + ty*8];
            float4 a1 = *(const float4*)&Qt[d*QT_S + ty*8 + 4];
            float4 kf = *(const float4*)&Kt[d*KT_S + tx*4];
            u64t kp0 = f2pk(kf.x, kf.y), kp1 = f2pk(kf.z, kf.w);
            float qa[8] = {a0.x,a0.y,a0.z,a0.w,a1.x,a1.y,a1.z,a1.w};
#pragma unroll
            for (int i = 0; i < 8; i++) {
                u64t qb = f2pk(qa[i], qa[i]);
                S2[i][0] = ffma2(qb, kp0, S2[i][0]);
                S2[i][1] = ffma2(qb, kp1, S2[i][1]);
            }
        }

        float bj0 = biasS[tx*4+0], bj1 = biasS[tx*4+1];
        float bj2 = biasS[tx*4+2], bj3 = biasS[tx*4+3];

#pragma unroll
        for (int i = 0; i < 8; i++) {
            float2 s01 = f2up(S2[i][0]);
            float2 s23 = f2up(S2[i][1]);
            float Sv[4];
            Sv[0] = s01.x*0.125f + bj0;
            Sv[1] = s01.y*0.125f + bj1;
            Sv[2] = s23.x*0.125f + bj2;
            Sv[3] = s23.y*0.125f + bj3;
            float rm = fmaxf(fmaxf(Sv[0], Sv[1]), fmaxf(Sv[2], Sv[3]));
#pragma unroll
            for (int off = 1; off < 16; off <<= 1)
                rm = fmaxf(rm, __shfl_xor_sync(0xffffffffu, rm, off));
            float mn = fmaxf(m[i], rm);
            float sc = __expf(m[i] - mn);
            float rs = 0.0f;
#pragma unroll
            for (int j = 0; j < 4; j++) {
                float p = __expf(Sv[j] - mn);
                Sv[j] = p;
                rs += p;
            }
#pragma unroll
            for (int off = 1; off < 16; off <<= 1)
                rs += __shfl_xor_sync(0xffffffffu, rs, off);
            l[i] = l[i] * sc + rs;
            m[i] = mn;
            u64t scp = f2pk(sc, sc);
            O2[i][0] = fmul2(O2[i][0], scp);
            O2[i][1] = fmul2(O2[i][1], scp);
            *(float4*)&Ps[(ty*8+i)*PS_S + tx*4] =
                make_float4(Sv[0], Sv[1], Sv[2], Sv[3]);
        }
        __syncwarp();

        // GEMM2: O += P V (packed pairs along value columns)
#pragma unroll 4
        for (int sc4 = 0; sc4 < 64; sc4 += 4) {
            float4 v0 = *(const float4*)&Vs[(sc4+0)*VS_S + tx*4];
            float4 v1 = *(const float4*)&Vs[(sc4+1)*VS_S + tx*4];
            float4 v2 = *(const float4*)&Vs[(sc4+2)*VS_S + tx*4];
            float4 v3 = *(const float4*)&Vs[(sc4+3)*VS_S + tx*4];
            u64t v0a = f2pk(v0.x,v0.y), v0b = f2pk(v0.z,v0.w);
            u64t v1a = f2pk(v1.x,v1.y), v1b = f2pk(v1.z,v1.w);
            u64t v2a = f2pk(v2.x,v2.y), v2b = f2pk(v2.z,v2.w);
            u64t v3a = f2pk(v3.x,v3.y), v3b = f2pk(v3.z,v3.w);
#pragma unroll
            for (int i = 0; i < 8; i++) {
                float4 p = *(const float4*)&Ps[(ty*8+i)*PS_S + sc4];
                u64t px = f2pk(p.x,p.x), py = f2pk(p.y,p.y);
                u64t pz = f2pk(p.z,p.z), pw = f2pk(p.w,p.w);
                O2[i][0] = ffma2(px, v0a, O2[i][0]);
                O2[i][0] = ffma2(py, v1a, O2[i][0]);
                O2[i][0] = ffma2(pz, v2a, O2[i][0]);
                O2[i][0] = ffma2(pw, v3a, O2[i][0]);
                O2[i][1] = ffma2(px, v0b, O2[i][1]);
                O2[i][1] = ffma2(py, v1b, O2[i][1]);
                O2[i][1] = ffma2(pz, v2b, O2[i][1]);
                O2[i][1] = ffma2(pw, v3b, O2[i][1]);
            }
        }
        __syncthreads();
    }

#pragma unroll
    for (int i = 0; i < 8; i++) {
        float inv = 1.0f / l[i];
        int row = q0 + ty*8 + i;
        float2 o01 = f2up(O2[i][0]);
        float2 o23 = f2up(O2[i][1]);
        float4 o = make_float4(o01.x*inv, o01.y*inv, o23.x*inv, o23.y*inv);
        *(float4*)&g_ctx[((size_t)b * LL + row) * CC + h * DD + tx*4] = o;
    }
}

// ---------------- launch -----------------------------------------------------
extern "C" void kernel_launch(void* const* d_in, const int* in_sizes, int n_in,
                              void* d_out, int out_size)
{
    const float* q  = (const float*)d_in[0];
    const void*  mk = d_in[1];
    const float* Wq = (const float*)d_in[2];
    const float* Wk = (const float*)d_in[3];
    const float* Wv = (const float*)d_in[4];
    const float* Wo = (const float*)d_in[5];
    const float* bo = (const float*)d_in[6];
    float* out = (float*)d_out;

    float* ctx;
    cudaGetSymbolAddress((void**)&ctx, g_ctx);

    const int smemB = FLASH_SMEM_FLOATS * (int)sizeof(float);
    cudaFuncSetAttribute(flash_kernel, cudaFuncAttributeMaxDynamicSharedMemorySize, smemB);

    detect_mask_kernel<<<1, 256>>>((const unsigned int*)mk);
    fill_bias_kernel<<<(BB*LL + 255) / 256, 256>>>(mk);
    rope_table_kernel<<<(LL*32 + 255) / 256, 256>>>();

    qkv_kernel<<<dim3(CC/128, ML/128, 3), 256>>>(q, Wq, Wk, Wv);

    int ropeN = BB * HH * LL * 32;
    rope_apply_kernel<<<(ropeN + 255) / 256, 256>>>();

    flash_kernel<<<dim3(LL/128, BB*HH), 256, smemB>>>();

    oproj_kernel<<<dim3(CC/128, ML/128), 256>>>(ctx, Wo, bo, out);
}

// round 6
// speedup vs baseline: 1.6181x; 1.4066x over previous
#include <cuda_runtime.h>
#include <cuda_bf16.h>
#include <math.h>
#include <cstdint>

#define BB 2
#define LL 2048
#define CC 1024
#define HH 16
#define DD 64
#define ML (BB*LL)

typedef unsigned long long u64t;

// ---------------- f32x2 packed helpers (flash kernel) -----------------------
__device__ __forceinline__ u64t f2pk(float lo, float hi) {
    u64t r; asm("mov.b64 %0, {%1, %2};" : "=l"(r) : "f"(lo), "f"(hi)); return r;
}
__device__ __forceinline__ u64t ffma2(u64t a, u64t b, u64t c) {
    u64t d; asm("fma.rn.f32x2 %0, %1, %2, %3;" : "=l"(d) : "l"(a), "l"(b), "l"(c)); return d;
}
__device__ __forceinline__ u64t fmul2(u64t a, u64t b) {
    u64t d; asm("mul.rn.f32x2 %0, %1, %2;" : "=l"(d) : "l"(a), "l"(b)); return d;
}
__device__ __forceinline__ float2 f2up(u64t v) {
    float2 f; asm("mov.b64 {%0, %1}, %2;" : "=f"(f.x), "=f"(f.y) : "l"(v)); return f;
}

// ---------------- HMMA helpers ----------------------------------------------
__device__ __forceinline__ uint32_t smem_u32(const void* p) {
    uint32_t a;
    asm("{ .reg .u64 t; cvta.to.shared.u64 t, %1; cvt.u32.u64 %0, t; }" : "=r"(a) : "l"(p));
    return a;
}
__device__ __forceinline__ void ldsm4(uint32_t* r, uint32_t addr) {
    asm volatile("ldmatrix.sync.aligned.m8n8.x4.shared.b16 {%0,%1,%2,%3}, [%4];"
        : "=r"(r[0]), "=r"(r[1]), "=r"(r[2]), "=r"(r[3]) : "r"(addr));
}
__device__ __forceinline__ void mma16816(float* c, const uint32_t* a, const uint32_t* b) {
    asm volatile("mma.sync.aligned.m16n8k16.row.col.f32.bf16.bf16.f32 "
        "{%0,%1,%2,%3}, {%4,%5,%6,%7}, {%8,%9}, {%0,%1,%2,%3};"
        : "+f"(c[0]), "+f"(c[1]), "+f"(c[2]), "+f"(c[3])
        : "r"(a[0]), "r"(a[1]), "r"(a[2]), "r"(a[3]), "r"(b[0]), "r"(b[1]));
}
__device__ __forceinline__ void cpasync16(uint32_t saddr, const void* g) {
    asm volatile("cp.async.cg.shared.global [%0], [%1], 16;" :: "r"(saddr), "l"(g));
}
#define CP_COMMIT() asm volatile("cp.async.commit_group;" ::: "memory")
#define CP_WAIT1()  asm volatile("cp.async.wait_group 1;" ::: "memory")
#define CP_WAIT0()  asm volatile("cp.async.wait_group 0;" ::: "memory")

// ---------------- scratch ----------------------------------------------------
__device__ float g_qh[BB*HH*LL*DD];
__device__ float g_kh[BB*HH*LL*DD];
__device__ float g_vh[BB*HH*LL*DD];
__device__ float g_ctx[BB*LL*CC];
__device__ float g_bias[BB*LL];
__device__ float2 g_ropeTab[LL*32];
__device__ int   g_maskfmt;
__device__ __nv_bfloat16 g_xhi[ML*CC], g_xlo[ML*CC];
__device__ __nv_bfloat16 g_whi[4*CC*CC], g_wlo[4*CC*CC];
__device__ __nv_bfloat16 g_chi[ML*CC], g_clo[ML*CC];

// ---------------- mask handling ---------------------------------------------
__global__ void detect_mask_kernel(const unsigned int* __restrict__ m) {
    __shared__ int s_i32, s_f32;
    if (threadIdx.x == 0) { s_i32 = 1; s_f32 = 1; }
    __syncthreads();
    int i32 = 1, f32 = 1;
    for (int i = threadIdx.x; i < 1024; i += 256) {
        unsigned v = m[i];
        if (v > 1u) i32 = 0;
        if (v != 0u && v != 0x3F800000u) f32 = 0;
    }
    if (!i32) atomicAnd(&s_i32, 0);
    if (!f32) atomicAnd(&s_f32, 0);
    __syncthreads();
    if (threadIdx.x == 0) g_maskfmt = s_i32 ? 0 : (s_f32 ? 1 : 2);
}

__global__ void fill_bias_kernel(const void* __restrict__ mp) {
    int i = blockIdx.x * 256 + threadIdx.x;
    if (i >= BB*LL) return;
    int fmt = g_maskfmt;
    bool on;
    if (fmt == 0)      on = ((const int*)mp)[i] != 0;
    else if (fmt == 1) on = ((const float*)mp)[i] != 0.0f;
    else               on = ((const unsigned char*)mp)[i] != 0;
    g_bias[i] = on ? 0.0f : -1e30f;
}

// ---------------- fp32 -> bf16 hi/lo split ----------------------------------
__global__ void split_kernel(const float* __restrict__ in, __nv_bfloat16* __restrict__ hi,
                             __nv_bfloat16* __restrict__ lo, int n) {
    int i = (blockIdx.x * 256 + threadIdx.x) * 4;
    if (i >= n) return;
    float4 v = *(const float4*)(in + i);
    __nv_bfloat16 h0 = __float2bfloat16_rn(v.x);
    __nv_bfloat16 h1 = __float2bfloat16_rn(v.y);
    __nv_bfloat16 h2 = __float2bfloat16_rn(v.z);
    __nv_bfloat16 h3 = __float2bfloat16_rn(v.w);
    __nv_bfloat16 l0 = __float2bfloat16_rn(v.x - __bfloat162float(h0));
    __nv_bfloat16 l1 = __float2bfloat16_rn(v.y - __bfloat162float(h1));
    __nv_bfloat16 l2 = __float2bfloat16_rn(v.z - __bfloat162float(h2));
    __nv_bfloat16 l3 = __float2bfloat16_rn(v.w - __bfloat162float(h3));
    __nv_bfloat162 hp0; hp0.x = h0; hp0.y = h1;
    __nv_bfloat162 hp1; hp1.x = h2; hp1.y = h3;
    __nv_bfloat162 lp0; lp0.x = l0; lp0.y = l1;
    __nv_bfloat162 lp1; lp1.x = l2; lp1.y = l3;
    *(__nv_bfloat162*)(hi + i)     = hp0;
    *(__nv_bfloat162*)(hi + i + 2) = hp1;
    *(__nv_bfloat162*)(lo + i)     = lp0;
    *(__nv_bfloat162*)(lo + i + 2) = lp1;
}

// ---------------- bf16-split HMMA NT GEMM -----------------------------------
// Block 128x128, 8 warps (warp tile 64x32), K-chunks of 32 bf16, cp.async DB.
// Tiles per buffer: Ahi, Alo, Bhi, Blo: each 128 rows x 32 bf16, stride 80 B.
#define TILE_B   10240                  /* 128*80 */
#define BUF_B    (4*TILE_B)             /* 40960 */
#define GM_SMEM  (2*BUF_B)              /* 81920 */

__global__ __launch_bounds__(256)
void gemm_mma_kernel(const __nv_bfloat16* __restrict__ Ahi, const __nv_bfloat16* __restrict__ Alo,
                     const __nv_bfloat16* __restrict__ WhiA, const __nv_bfloat16* __restrict__ WloA,
                     const float* __restrict__ bias, float* __restrict__ oout, int is_oproj)
{
    extern __shared__ __align__(128) char smem[];
    const uint32_t sb = smem_u32(smem);
    const int tid  = threadIdx.x;
    const int warp = tid >> 5;
    const int lane = tid & 31;
    const int bm = blockIdx.y * 128;
    const int bn = blockIdx.x * 128;
    const int z  = blockIdx.z;

    const __nv_bfloat16* Whi = WhiA + (size_t)z * CC * CC;
    const __nv_bfloat16* Wlo = WloA + (size_t)z * CC * CC;

    // ---- cp.async thread mapping: tile t = tid>>6, u = tid&63
    const int lt = tid >> 6;            // 0..3 : Ahi, Alo, Bhi, Blo
    const int u  = tid & 63;
    const int lrow = u >> 2;            // 0..15 (stepped by 16)
    const int lc16 = u & 3;             // 16B column
    const __nv_bfloat16* lsrc =
        (lt == 0) ? Ahi : (lt == 1) ? Alo : (lt == 2) ? Whi : Wlo;
    const int lbase_row = (lt < 2) ? bm : bn;
    const uint32_t s_store0 = sb + lt * TILE_B + lc16 * 16;

    // prefetch chunk 0 into buffer 0
    {
        const int k0 = 0;
#pragma unroll
        for (int j = 0; j < 8; j++) {
            int row = j * 16 + lrow;
            cpasync16(s_store0 + row * 80,
                      lsrc + (size_t)(lbase_row + row) * CC + k0 + lc16 * 8);
        }
        CP_COMMIT();
    }

    // ---- fragment addresses
    const int wm = (warp >> 2) * 64;    // warp row offset
    const int wn = (warp & 3) * 32;     // warp col offset
    // A: tile tm (0..3), kstep ks (0..1), dtype 0=hi 1=lo
    uint32_t aoff[2][4][2];
#pragma unroll
    for (int dt = 0; dt < 2; dt++)
#pragma unroll
        for (int tm = 0; tm < 4; tm++)
#pragma unroll
            for (int ks = 0; ks < 2; ks++)
                aoff[dt][tm][ks] = sb + dt * TILE_B
                    + (wm + tm * 16 + (lane & 15)) * 80 + ks * 32 + (lane >> 4) * 16;
    // B: tile tn (0..3), dtype
    uint32_t boff[2][4];
#pragma unroll
    for (int dt = 0; dt < 2; dt++)
#pragma unroll
        for (int tn = 0; tn < 4; tn++)
            boff[dt][tn] = sb + (2 + dt) * TILE_B
                + (wn + tn * 8 + (lane & 7)) * 80 + ((lane >> 3) & 3) * 16;

    float acc[4][4][4];
#pragma unroll
    for (int tm = 0; tm < 4; tm++)
#pragma unroll
        for (int tn = 0; tn < 4; tn++)
#pragma unroll
            for (int c = 0; c < 4; c++) acc[tm][tn][c] = 0.0f;

    int buf = 0;
    for (int ch = 0; ch < 32; ch++) {
        if (ch + 1 < 32) {
            const int k0 = (ch + 1) * 32;
            const uint32_t sdst = s_store0 + (buf ^ 1) * BUF_B;
#pragma unroll
            for (int j = 0; j < 8; j++) {
                int row = j * 16 + lrow;
                cpasync16(sdst + row * 80,
                          lsrc + (size_t)(lbase_row + row) * CC + k0 + lc16 * 8);
            }
            CP_COMMIT();
            CP_WAIT1();
        } else {
            CP_WAIT0();
        }
        __syncthreads();

        const uint32_t bo = buf * BUF_B;
        uint32_t bh[4][4], bl[4][4];
#pragma unroll
        for (int tn = 0; tn < 4; tn++) {
            ldsm4(bh[tn], boff[0][tn] + bo);
            ldsm4(bl[tn], boff[1][tn] + bo);
        }
#pragma unroll
        for (int ks = 0; ks < 2; ks++) {
#pragma unroll
            for (int tm = 0; tm < 4; tm++) {
                uint32_t ah[4], al[4];
                ldsm4(ah, aoff[0][tm][ks] + bo);
                ldsm4(al, aoff[1][tm][ks] + bo);
#pragma unroll
                for (int tn = 0; tn < 4; tn++) {
                    mma16816(acc[tm][tn], ah, &bh[tn][ks * 2]);
                    mma16816(acc[tm][tn], ah, &bl[tn][ks * 2]);
                    mma16816(acc[tm][tn], al, &bh[tn][ks * 2]);
                }
            }
        }
        __syncthreads();
        buf ^= 1;
    }

    // ---- epilogue
    const int rbase = bm + wm + (lane >> 2);
    const int cbase = bn + wn + (lane & 3) * 2;
#pragma unroll
    for (int tm = 0; tm < 4; tm++) {
#pragma unroll
        for (int tn = 0; tn < 4; tn++) {
            int row0 = rbase + tm * 16;
            int col  = cbase + tn * 8;
            if (is_oproj) {
                float b0 = bias[col], b1 = bias[col + 1];
                *(float2*)&oout[(size_t)row0 * CC + col] =
                    make_float2(acc[tm][tn][0] + b0, acc[tm][tn][1] + b1);
                *(float2*)&oout[(size_t)(row0 + 8) * CC + col] =
                    make_float2(acc[tm][tn][2] + b0, acc[tm][tn][3] + b1);
            } else {
                float* out = (z == 0) ? g_qh : (z == 1) ? g_kh : g_vh;
                const int h = col >> 6, d = col & 63;
                {
                    int b = row0 >> 11, l = row0 & (LL - 1);
                    *(float2*)&out[(((size_t)b * HH + h) * LL + l) * DD + d] =
                        make_float2(acc[tm][tn][0], acc[tm][tn][1]);
                }
                {
                    int r1 = row0 + 8;
                    int b = r1 >> 11, l = r1 & (LL - 1);
                    *(float2*)&out[(((size_t)b * HH + h) * LL + l) * DD + d] =
                        make_float2(acc[tm][tn][2], acc[tm][tn][3]);
                }
            }
        }
    }
}

// ---------------- RoPE ------------------------------------------------------
__global__ void rope_table_kernel() {
    int gid = blockIdx.x * 256 + threadIdx.x;
    if (gid >= LL*32) return;
    int d = gid & 31, l = gid >> 5;
    double inv = exp(-10.819778284410283 * (double)(2 * d) / 64.0);  // ln(50000)
    double sn, cs;
    sincos((double)l * inv, &sn, &cs);
    g_ropeTab[gid] = make_float2((float)cs, (float)sn);
}

__global__ void rope_apply_kernel() {
    int gid = blockIdx.x * 256 + threadIdx.x;
    if (gid >= BB*HH*LL*32) return;
    int d   = gid & 31;
    int row = gid >> 5;
    int l   = row & (LL - 1);
    float2 cs = g_ropeTab[l * 32 + d];
    float c = cs.x, s = cs.y;
    float* qp = g_qh + (size_t)row * DD;
    float* kp = g_kh + (size_t)row * DD;
    float a = qp[d], b2 = qp[d + 32];
    qp[d]      = a  * c - b2 * s;
    qp[d + 32] = b2 * c + a  * s;
    float ak = kp[d], bk = kp[d + 32];
    kp[d]      = ak * c - bk * s;
    kp[d + 32] = bk * c + ak * s;
}

// ---------------- Flash attention: 128x64 tiles, f32x2 math -----------------
#define QT_S 132
#define KT_S 68
#define VS_S 68
#define PS_S 68
#define OFF_KT 8448
#define OFF_VS 12800
#define OFF_PS 17152
#define OFF_BI 25856
#define FLASH_SMEM_FLOATS 25920

__global__ __launch_bounds__(256)
void flash_kernel()
{
    extern __shared__ float smf[];
    float* Qt = smf;
    float* Kt = smf + OFF_KT;
    float* Vs = smf + OFF_VS;
    float* Ps = smf + OFF_PS;
    float* biasS = smf + OFF_BI;

    const int q0 = blockIdx.x * 128;
    const int bh = blockIdx.y;
    const int b  = bh >> 4;
    const int h  = bh & 15;
    const int tid = threadIdx.x;
    const int ty = tid >> 4, tx = tid & 15;

    const float* qbase = g_qh + (size_t)bh * LL * DD;
    const float* kbase = g_kh + (size_t)bh * LL * DD;
    const float* vbase = g_vh + (size_t)bh * LL * DD;

    {
        const int r = tid & 127, hf = tid >> 7;
        const float* qp = qbase + (size_t)(q0 + r) * DD + hf * 32;
#pragma unroll
        for (int j = 0; j < 8; j++) {
            float4 v = *(const float4*)(qp + j * 4);
            int d0 = hf * 32 + j * 4;
            Qt[(d0+0)*QT_S + r] = v.x; Qt[(d0+1)*QT_S + r] = v.y;
            Qt[(d0+2)*QT_S + r] = v.z; Qt[(d0+3)*QT_S + r] = v.w;
        }
    }

    u64t O2[8][2];
    float m[8], l[8];
#pragma unroll
    for (int i = 0; i < 8; i++) {
        m[i] = -1e30f; l[i] = 0.0f;
        O2[i][0] = 0ULL; O2[i][1] = 0ULL;
    }

    const int c64 = tid & 63, dh = tid >> 6;

    for (int s0 = 0; s0 < LL; s0 += 64) {
        {
            const float* kp = kbase + (size_t)(s0 + c64) * DD + dh * 16;
            const float* vp = vbase + (size_t)(s0 + c64) * DD + dh * 16;
#pragma unroll
            for (int j = 0; j < 4; j++) {
                float4 kv = *(const float4*)(kp + j * 4);
                int d0 = dh * 16 + j * 4;
                Kt[(d0+0)*KT_S + c64] = kv.x; Kt[(d0+1)*KT_S + c64] = kv.y;
                Kt[(d0+2)*KT_S + c64] = kv.z; Kt[(d0+3)*KT_S + c64] = kv.w;
                float4 vv = *(const float4*)(vp + j * 4);
                *(float4*)&Vs[c64 * VS_S + d0] = vv;
            }
            if (tid < 64) biasS[tid] = g_bias[b * LL + s0 + tid];
        }
        __syncthreads();

        u64t S2[8][2];
#pragma unroll
        for (int i = 0; i < 8; i++) { S2[i][0] = 0ULL; S2[i][1] = 0ULL; }
#pragma unroll 8
        for (int d = 0; d < 64; d++) {
            float4 a0 = *(const float4*)&Qt[d*QT_S + ty*8];
            float4 a1 = *(const float4*)&Qt[d*QT_S + ty*8 + 4];
            float4 kf = *(const float4*)&Kt[d*KT_S + tx*4];
            u64t kp0 = f2pk(kf.x, kf.y), kp1 = f2pk(kf.z, kf.w);
            float qa[8] = {a0.x,a0.y,a0.z,a0.w,a1.x,a1.y,a1.z,a1.w};
#pragma unroll
            for (int i = 0; i < 8; i++) {
                u64t qb = f2pk(qa[i], qa[i]);
                S2[i][0] = ffma2(qb, kp0, S2[i][0]);
                S2[i][1] = ffma2(qb, kp1, S2[i][1]);
            }
        }

        float bj0 = biasS[tx*4+0], bj1 = biasS[tx*4+1];
        float bj2 = biasS[tx*4+2], bj3 = biasS[tx*4+3];

#pragma unroll
        for (int i = 0; i < 8; i++) {
            float2 s01 = f2up(S2[i][0]);
            float2 s23 = f2up(S2[i][1]);
            float Sv[4];
            Sv[0] = s01.x*0.125f + bj0;
            Sv[1] = s01.y*0.125f + bj1;
            Sv[2] = s23.x*0.125f + bj2;
            Sv[3] = s23.y*0.125f + bj3;
            float rm = fmaxf(fmaxf(Sv[0], Sv[1]), fmaxf(Sv[2], Sv[3]));
#pragma unroll
            for (int off = 1; off < 16; off <<= 1)
                rm = fmaxf(rm, __shfl_xor_sync(0xffffffffu, rm, off));
            float mn = fmaxf(m[i], rm);
            float sc = __expf(m[i] - mn);
            float rs = 0.0f;
#pragma unroll
            for (int j = 0; j < 4; j++) {
                float p = __expf(Sv[j] - mn);
                Sv[j] = p;
                rs += p;
            }
#pragma unroll
            for (int off = 1; off < 16; off <<= 1)
                rs += __shfl_xor_sync(0xffffffffu, rs, off);
            l[i] = l[i] * sc + rs;
            m[i] = mn;
            u64t scp = f2pk(sc, sc);
            O2[i][0] = fmul2(O2[i][0], scp);
            O2[i][1] = fmul2(O2[i][1], scp);
            *(float4*)&Ps[(ty*8+i)*PS_S + tx*4] =
                make_float4(Sv[0], Sv[1], Sv[2], Sv[3]);
        }
        __syncwarp();

#pragma unroll 4
        for (int sc4 = 0; sc4 < 64; sc4 += 4) {
            float4 v0 = *(const float4*)&Vs[(sc4+0)*VS_S + tx*4];
            float4 v1 = *(const float4*)&Vs[(sc4+1)*VS_S + tx*4];
            float4 v2 = *(const float4*)&Vs[(sc4+2)*VS_S + tx*4];
            float4 v3 = *(const float4*)&Vs[(sc4+3)*VS_S + tx*4];
            u64t v0a = f2pk(v0.x,v0.y), v0b = f2pk(v0.z,v0.w);
            u64t v1a = f2pk(v1.x,v1.y), v1b = f2pk(v1.z,v1.w);
            u64t v2a = f2pk(v2.x,v2.y), v2b = f2pk(v2.z,v2.w);
            u64t v3a = f2pk(v3.x,v3.y), v3b = f2pk(v3.z,v3.w);
#pragma unroll
            for (int i = 0; i < 8; i++) {
                float4 p = *(const float4*)&Ps[(ty*8+i)*PS_S + sc4];
                u64t px = f2pk(p.x,p.x), py = f2pk(p.y,p.y);
                u64t pz = f2pk(p.z,p.z), pw = f2pk(p.w,p.w);
                O2[i][0] = ffma2(px, v0a, O2[i][0]);
                O2[i][0] = ffma2(py, v1a, O2[i][0]);
                O2[i][0] = ffma2(pz, v2a, O2[i][0]);
                O2[i][0] = ffma2(pw, v3a, O2[i][0]);
                O2[i][1] = ffma2(px, v0b, O2[i][1]);
                O2[i][1] = ffma2(py, v1b, O2[i][1]);
                O2[i][1] = ffma2(pz, v2b, O2[i][1]);
                O2[i][1] = ffma2(pw, v3b, O2[i][1]);
            }
        }
        __syncthreads();
    }

#pragma unroll
    for (int i = 0; i < 8; i++) {
        float inv = 1.0f / l[i];
        int row = q0 + ty*8 + i;
        float2 o01 = f2up(O2[i][0]);
        float2 o23 = f2up(O2[i][1]);
        float4 o = make_float4(o01.x*inv, o01.y*inv, o23.x*inv, o23.y*inv);
        *(float4*)&g_ctx[((size_t)b * LL + row) * CC + h * DD + tx*4] = o;
    }
}

// ---------------- launch -----------------------------------------------------
extern "C" void kernel_launch(void* const* d_in, const int* in_sizes, int n_in,
                              void* d_out, int out_size)
{
    const float* q  = (const float*)d_in[0];
    const void*  mk = d_in[1];
    const float* Wq = (const float*)d_in[2];
    const float* Wk = (const float*)d_in[3];
    const float* Wv = (const float*)d_in[4];
    const float* Wo = (const float*)d_in[5];
    const float* bo = (const float*)d_in[6];
    float* out = (float*)d_out;

    float *ctx;
    __nv_bfloat16 *xhi, *xlo, *whi, *wlo, *chi, *clo;
    cudaGetSymbolAddress((void**)&ctx, g_ctx);
    cudaGetSymbolAddress((void**)&xhi, g_xhi);
    cudaGetSymbolAddress((void**)&xlo, g_xlo);
    cudaGetSymbolAddress((void**)&whi, g_whi);
    cudaGetSymbolAddress((void**)&wlo, g_wlo);
    cudaGetSymbolAddress((void**)&chi, g_chi);
    cudaGetSymbolAddress((void**)&clo, g_clo);

    const int flashSmem = FLASH_SMEM_FLOATS * (int)sizeof(float);
    cudaFuncSetAttribute(flash_kernel, cudaFuncAttributeMaxDynamicSharedMemorySize, flashSmem);
    cudaFuncSetAttribute(gemm_mma_kernel, cudaFuncAttributeMaxDynamicSharedMemorySize, GM_SMEM);

    detect_mask_kernel<<<1, 256>>>((const unsigned int*)mk);
    fill_bias_kernel<<<(BB*LL + 255) / 256, 256>>>(mk);
    rope_table_kernel<<<(LL*32 + 255) / 256, 256>>>();

    const int nx = ML * CC;
    const int nw = CC * CC;
    split_kernel<<<(nx/4 + 255) / 256, 256>>>(q,  xhi, xlo, nx);
    split_kernel<<<(nw/4 + 255) / 256, 256>>>(Wq, whi + 0*(size_t)nw, wlo + 0*(size_t)nw, nw);
    split_kernel<<<(nw/4 + 255) / 256, 256>>>(Wk, whi + 1*(size_t)nw, wlo + 1*(size_t)nw, nw);
    split_kernel<<<(nw/4 + 255) / 256, 256>>>(Wv, whi + 2*(size_t)nw, wlo + 2*(size_t)nw, nw);
    split_kernel<<<(nw/4 + 255) / 256, 256>>>(Wo, whi + 3*(size_t)nw, wlo + 3*(size_t)nw, nw);

    gemm_mma_kernel<<<dim3(CC/128, ML/128, 3), 256, GM_SMEM>>>(
        xhi, xlo, whi, wlo, nullptr, nullptr, 0);

    int ropeN = BB * HH * LL * 32;
    rope_apply_kernel<<<(ropeN + 255) / 256, 256>>>();

    flash_kernel<<<dim3(LL/128, BB*HH), 256, flashSmem>>>();

    split_kernel<<<(nx/4 + 255) / 256, 256>>>(ctx, chi, clo, nx);
    gemm_mma_kernel<<<dim3(CC/128, ML/128, 1), 256, GM_SMEM>>>(
        chi, clo, whi + 3*(size_t)nw, wlo + 3*(size_t)nw, bo, out, 1);
}

// round 8
// speedup vs baseline: 3.5631x; 2.2020x over previous
#include <cuda_runtime.h>
#include <cuda_bf16.h>
#include <cuda_fp16.h>
#include <math.h>
#include <cstdint>

#define BB 2
#define LL 2048
#define CC 1024
#define HH 16
#define DD 64
#define ML (BB*LL)

// ---------------- MMA / ldmatrix helpers ------------------------------------
__device__ __forceinline__ uint32_t smem_u32(const void* p) {
    uint32_t a;
    asm("{ .reg .u64 t; cvta.to.shared.u64 t, %1; cvt.u32.u64 %0, t; }" : "=r"(a) : "l"(p));
    return a;
}
__device__ __forceinline__ void ldsm4(uint32_t* r, uint32_t addr) {
    asm volatile("ldmatrix.sync.aligned.m8n8.x4.shared.b16 {%0,%1,%2,%3}, [%4];"
        : "=r"(r[0]), "=r"(r[1]), "=r"(r[2]), "=r"(r[3]) : "r"(addr));
}
__device__ __forceinline__ void ldsm4t(uint32_t* r, uint32_t addr) {
    asm volatile("ldmatrix.sync.aligned.m8n8.x4.trans.shared.b16 {%0,%1,%2,%3}, [%4];"
        : "=r"(r[0]), "=r"(r[1]), "=r"(r[2]), "=r"(r[3]) : "r"(addr));
}
__device__ __forceinline__ void mma_bf16(float* c, const uint32_t* a, const uint32_t* b) {
    asm volatile("mma.sync.aligned.m16n8k16.row.col.f32.bf16.bf16.f32 "
        "{%0,%1,%2,%3}, {%4,%5,%6,%7}, {%8,%9}, {%0,%1,%2,%3};"
        : "+f"(c[0]), "+f"(c[1]), "+f"(c[2]), "+f"(c[3])
        : "r"(a[0]), "r"(a[1]), "r"(a[2]), "r"(a[3]), "r"(b[0]), "r"(b[1]));
}
__device__ __forceinline__ void mma_f16(float* c, const uint32_t* a, const uint32_t* b) {
    asm volatile("mma.sync.aligned.m16n8k16.row.col.f32.f16.f16.f32 "
        "{%0,%1,%2,%3}, {%4,%5,%6,%7}, {%8,%9}, {%0,%1,%2,%3};"
        : "+f"(c[0]), "+f"(c[1]), "+f"(c[2]), "+f"(c[3])
        : "r"(a[0]), "r"(a[1]), "r"(a[2]), "r"(a[3]), "r"(b[0]), "r"(b[1]));
}
__device__ __forceinline__ void cpasync16(uint32_t saddr, const void* g) {
    asm volatile("cp.async.cg.shared.global [%0], [%1], 16;" :: "r"(saddr), "l"(g));
}
#define CP_COMMIT() asm volatile("cp.async.commit_group;" ::: "memory")
#define CP_WAIT1()  asm volatile("cp.async.wait_group 1;" ::: "memory")
#define CP_WAIT0()  asm volatile("cp.async.wait_group 0;" ::: "memory")

// ---------------- scratch ----------------------------------------------------
__device__ float  g_qh[BB*HH*LL*DD];          // fp32 Q heads (pre-RoPE)
__device__ float  g_kh[BB*HH*LL*DD];
__device__ __half g_qhh[BB*HH*LL*DD];         // fp16 post-RoPE
__device__ __half g_khh[BB*HH*LL*DD];
__device__ __half g_vhh[BB*HH*LL*DD];
__device__ float  g_bias[BB*LL];
__device__ float2 g_ropeTab[LL*32];
__device__ int    g_maskfmt;
__device__ __nv_bfloat16 g_xhi[ML*CC], g_xlo[ML*CC];
__device__ __nv_bfloat16 g_whi[4*CC*CC], g_wlo[4*CC*CC];
__device__ __nv_bfloat16 g_chi[ML*CC], g_clo[ML*CC];

// ---------------- mask handling ---------------------------------------------
__global__ void detect_mask_kernel(const unsigned int* __restrict__ m) {
    __shared__ int s_i32, s_f32;
    if (threadIdx.x == 0) { s_i32 = 1; s_f32 = 1; }
    __syncthreads();
    int i32 = 1, f32 = 1;
    for (int i = threadIdx.x; i < 1024; i += 256) {
        unsigned v = m[i];
        if (v > 1u) i32 = 0;
        if (v != 0u && v != 0x3F800000u) f32 = 0;
    }
    if (!i32) atomicAnd(&s_i32, 0);
    if (!f32) atomicAnd(&s_f32, 0);
    __syncthreads();
    if (threadIdx.x == 0) g_maskfmt = s_i32 ? 0 : (s_f32 ? 1 : 2);
}

__global__ void fill_bias_kernel(const void* __restrict__ mp) {
    int i = blockIdx.x * 256 + threadIdx.x;
    if (i >= BB*LL) return;
    int fmt = g_maskfmt;
    bool on;
    if (fmt == 0)      on = ((const int*)mp)[i] != 0;
    else if (fmt == 1) on = ((const float*)mp)[i] != 0.0f;
    else               on = ((const unsigned char*)mp)[i] != 0;
    g_bias[i] = on ? 0.0f : -1e30f;
}

// ---------------- fp32 -> bf16 hi/lo split ----------------------------------
__global__ void split_kernel(const float* __restrict__ in, __nv_bfloat16* __restrict__ hi,
                             __nv_bfloat16* __restrict__ lo, int n) {
    int i = (blockIdx.x * 256 + threadIdx.x) * 4;
    if (i >= n) return;
    float4 v = *(const float4*)(in + i);
    __nv_bfloat16 h0 = __float2bfloat16_rn(v.x);
    __nv_bfloat16 h1 = __float2bfloat16_rn(v.y);
    __nv_bfloat16 h2 = __float2bfloat16_rn(v.z);
    __nv_bfloat16 h3 = __float2bfloat16_rn(v.w);
    __nv_bfloat16 l0 = __float2bfloat16_rn(v.x - __bfloat162float(h0));
    __nv_bfloat16 l1 = __float2bfloat16_rn(v.y - __bfloat162float(h1));
    __nv_bfloat16 l2 = __float2bfloat16_rn(v.z - __bfloat162float(h2));
    __nv_bfloat16 l3 = __float2bfloat16_rn(v.w - __bfloat162float(h3));
    __nv_bfloat162 hp0; hp0.x = h0; hp0.y = h1;
    __nv_bfloat162 hp1; hp1.x = h2; hp1.y = h3;
    __nv_bfloat162 lp0; lp0.x = l0; lp0.y = l1;
    __nv_bfloat162 lp1; lp1.x = l2; lp1.y = l3;
    *(__nv_bfloat162*)(hi + i)     = hp0;
    *(__nv_bfloat162*)(hi + i + 2) = hp1;
    *(__nv_bfloat162*)(lo + i)     = lp0;
    *(__nv_bfloat162*)(lo + i + 2) = lp1;
}

// ---------------- bf16-split HMMA NT GEMM (projections) ---------------------
#define TILE_B   10240
#define BUF_B    (4*TILE_B)
#define GM_SMEM  (2*BUF_B)

__global__ __launch_bounds__(256)
void gemm_mma_kernel(const __nv_bfloat16* __restrict__ Ahi, const __nv_bfloat16* __restrict__ Alo,
                     const __nv_bfloat16* __restrict__ WhiA, const __nv_bfloat16* __restrict__ WloA,
                     const float* __restrict__ bias, float* __restrict__ oout, int is_oproj)
{
    extern __shared__ __align__(128) char smem[];
    const uint32_t sb = smem_u32(smem);
    const int tid  = threadIdx.x;
    const int warp = tid >> 5;
    const int lane = tid & 31;
    const int bm = blockIdx.y * 128;
    const int bn = blockIdx.x * 128;
    const int z  = blockIdx.z;

    const __nv_bfloat16* Whi = WhiA + (size_t)z * CC * CC;
    const __nv_bfloat16* Wlo = WloA + (size_t)z * CC * CC;

    const int lt = tid >> 6;
    const int u  = tid & 63;
    const int lrow = u >> 2;
    const int lc16 = u & 3;
    const __nv_bfloat16* lsrc =
        (lt == 0) ? Ahi : (lt == 1) ? Alo : (lt == 2) ? Whi : Wlo;
    const int lbase_row = (lt < 2) ? bm : bn;
    const uint32_t s_store0 = sb + lt * TILE_B + lc16 * 16;

    {
#pragma unroll
        for (int j = 0; j < 8; j++) {
            int row = j * 16 + lrow;
            cpasync16(s_store0 + row * 80,
                      lsrc + (size_t)(lbase_row + row) * CC + lc16 * 8);
        }
        CP_COMMIT();
    }

    const int wm = (warp >> 2) * 64;
    const int wn = (warp & 3) * 32;
    uint32_t aoff[2][4][2];
#pragma unroll
    for (int dt = 0; dt < 2; dt++)
#pragma unroll
        for (int tm = 0; tm < 4; tm++)
#pragma unroll
            for (int ks = 0; ks < 2; ks++)
                aoff[dt][tm][ks] = sb + dt * TILE_B
                    + (wm + tm * 16 + (lane & 15)) * 80 + ks * 32 + (lane >> 4) * 16;
    uint32_t boff[2][4];
#pragma unroll
    for (int dt = 0; dt < 2; dt++)
#pragma unroll
        for (int tn = 0; tn < 4; tn++)
            boff[dt][tn] = sb + (2 + dt) * TILE_B
                + (wn + tn * 8 + (lane & 7)) * 80 + ((lane >> 3) & 3) * 16;

    float acc[4][4][4];
#pragma unroll
    for (int tm = 0; tm < 4; tm++)
#pragma unroll
        for (int tn = 0; tn < 4; tn++)
#pragma unroll
            for (int c = 0; c < 4; c++) acc[tm][tn][c] = 0.0f;

    int buf = 0;
    for (int ch = 0; ch < 32; ch++) {
        if (ch + 1 < 32) {
            const int k0 = (ch + 1) * 32;
            const uint32_t sdst = s_store0 + (buf ^ 1) * BUF_B;
#pragma unroll
            for (int j = 0; j < 8; j++) {
                int row = j * 16 + lrow;
                cpasync16(sdst + row * 80,
                          lsrc + (size_t)(lbase_row + row) * CC + k0 + lc16 * 8);
            }
            CP_COMMIT();
            CP_WAIT1();
        } else {
            CP_WAIT0();
        }
        __syncthreads();

        const uint32_t bo = buf * BUF_B;
        uint32_t bh[4][4], bl[4][4];
#pragma unroll
        for (int tn = 0; tn < 4; tn++) {
            ldsm4(bh[tn], boff[0][tn] + bo);
            ldsm4(bl[tn], boff[1][tn] + bo);
        }
#pragma unroll
        for (int ks = 0; ks < 2; ks++) {
#pragma unroll
            for (int tm = 0; tm < 4; tm++) {
                uint32_t ah[4], al[4];
                ldsm4(ah, aoff[0][tm][ks] + bo);
                ldsm4(al, aoff[1][tm][ks] + bo);
#pragma unroll
                for (int tn = 0; tn < 4; tn++) {
                    mma_bf16(acc[tm][tn], ah, &bh[tn][ks * 2]);
                    mma_bf16(acc[tm][tn], ah, &bl[tn][ks * 2]);
                    mma_bf16(acc[tm][tn], al, &bh[tn][ks * 2]);
                }
            }
        }
        __syncthreads();
        buf ^= 1;
    }

    const int rbase = bm + wm + (lane >> 2);
    const int cbase = bn + wn + (lane & 3) * 2;
#pragma unroll
    for (int tm = 0; tm < 4; tm++) {
#pragma unroll
        for (int tn = 0; tn < 4; tn++) {
            int row0 = rbase + tm * 16;
            int col  = cbase + tn * 8;
            if (is_oproj) {
                float b0 = bias[col], b1 = bias[col + 1];
                *(float2*)&oout[(size_t)row0 * CC + col] =
                    make_float2(acc[tm][tn][0] + b0, acc[tm][tn][1] + b1);
                *(float2*)&oout[(size_t)(row0 + 8) * CC + col] =
                    make_float2(acc[tm][tn][2] + b0, acc[tm][tn][3] + b1);
            } else if (z == 2) {
                // V -> fp16 heads directly
                const int h = col >> 6, d = col & 63;
                {
                    int b = row0 >> 11, l = row0 & (LL - 1);
                    *(__half2*)&g_vhh[(((size_t)b * HH + h) * LL + l) * DD + d] =
                        __floats2half2_rn(acc[tm][tn][0], acc[tm][tn][1]);
                }
                {
                    int r1 = row0 + 8;
                    int b = r1 >> 11, l = r1 & (LL - 1);
                    *(__half2*)&g_vhh[(((size_t)b * HH + h) * LL + l) * DD + d] =
                        __floats2half2_rn(acc[tm][tn][2], acc[tm][tn][3]);
                }
            } else {
                float* out = (z == 0) ? g_qh : g_kh;
                const int h = col >> 6, d = col & 63;
                {
                    int b = row0 >> 11, l = row0 & (LL - 1);
                    *(float2*)&out[(((size_t)b * HH + h) * LL + l) * DD + d] =
                        make_float2(acc[tm][tn][0], acc[tm][tn][1]);
                }
                {
                    int r1 = row0 + 8;
                    int b = r1 >> 11, l = r1 & (LL - 1);
                    *(float2*)&out[(((size_t)b * HH + h) * LL + l) * DD + d] =
                        make_float2(acc[tm][tn][2], acc[tm][tn][3]);
                }
            }
        }
    }
}

// ---------------- RoPE ------------------------------------------------------
__global__ void rope_table_kernel() {
    int gid = blockIdx.x * 256 + threadIdx.x;
    if (gid >= LL*32) return;
    int d = gid & 31, l = gid >> 5;
    double inv = exp(-10.819778284410283 * (double)(2 * d) / 64.0);  // ln(50000)
    double sn, cs;
    sincos((double)l * inv, &sn, &cs);
    g_ropeTab[gid] = make_float2((float)cs, (float)sn);
}

// reads fp32 heads, applies rotation, writes fp16 heads
__global__ void rope_apply_kernel() {
    int gid = blockIdx.x * 256 + threadIdx.x;
    if (gid >= BB*HH*LL*32) return;
    int d   = gid & 31;
    int row = gid >> 5;
    int l   = row & (LL - 1);
    float2 cs = g_ropeTab[l * 32 + d];
    float c = cs.x, s = cs.y;
    const float* qp = g_qh + (size_t)row * DD;
    const float* kp = g_kh + (size_t)row * DD;
    __half* qo = g_qhh + (size_t)row * DD;
    __half* ko = g_khh + (size_t)row * DD;
    float a = qp[d], b2 = qp[d + 32];
    qo[d]      = __float2half_rn(a  * c - b2 * s);
    qo[d + 32] = __float2half_rn(b2 * c + a  * s);
    float ak = kp[d], bk = kp[d + 32];
    ko[d]      = __float2half_rn(ak * c - bk * s);
    ko[d + 32] = __float2half_rn(bk * c + ak * s);
}

// ---------------- Flash attention: fp16 HMMA + h2exp ------------------------
// Block: 256 thr (8 warps), 128 q-rows, key-tiles of 64, D=64.
// smem (bytes): Q 128x144=18432 | K 2x64x144 | V 2x64x144 | bias 2x64xf32
#define FOFF_K  18432
#define FOFF_V  36864
#define FOFF_BI 55296
#define FL_SMEM 55808

__global__ __launch_bounds__(256)
void flash_kernel()
{
    extern __shared__ __align__(128) char smx[];
    const uint32_t sb = smem_u32(smx);
    float* biasS = (float*)(smx + FOFF_BI);

    const int q0 = blockIdx.x * 128;
    const int bh = blockIdx.y;
    const int b  = bh >> 4;
    const int h  = bh & 15;
    const int tid  = threadIdx.x;
    const int warp = tid >> 5;
    const int lane = tid & 31;

    const __half* qb = g_qhh + (size_t)bh * LL * DD;
    const __half* kb = g_khh + (size_t)bh * LL * DD;
    const __half* vb = g_vhh + (size_t)bh * LL * DD;

    // stage Q (persistent) + K/V tile 0
    {
#pragma unroll
        for (int j = 0; j < 4; j++) {
            int t = tid + j * 256;              // 1024 tasks
            int row = t >> 3, ch = t & 7;
            cpasync16(sb + row * 144 + ch * 16, qb + (size_t)(q0 + row) * DD + ch * 8);
        }
#pragma unroll
        for (int j = 0; j < 2; j++) {
            int t = tid + j * 256;              // 512 tasks
            int row = t >> 3, ch = t & 7;
            cpasync16(sb + FOFF_K + row * 144 + ch * 16, kb + (size_t)row * DD + ch * 8);
            cpasync16(sb + FOFF_V + row * 144 + ch * 16, vb + (size_t)row * DD + ch * 8);
        }
        if (tid < 64) biasS[tid] = g_bias[b * LL + tid];
        CP_COMMIT();
    }

    float O[8][4];
    float m0 = -1e30f, m1 = -1e30f, l0 = 0.0f, l1 = 0.0f;
#pragma unroll
    for (int nt = 0; nt < 8; nt++)
#pragma unroll
        for (int c = 0; c < 4; c++) O[nt][c] = 0.0f;

    uint32_t aQ[4][4];

    int buf = 0;
    for (int ch = 0; ch < 32; ch++) {
        if (ch + 1 < 32) {
            const int s1 = (ch + 1) * 64;
            const uint32_t ko = FOFF_K + (buf ^ 1) * 9216;
            const uint32_t vo = FOFF_V + (buf ^ 1) * 9216;
#pragma unroll
            for (int j = 0; j < 2; j++) {
                int t = tid + j * 256;
                int row = t >> 3, c16 = t & 7;
                cpasync16(sb + ko + row * 144 + c16 * 16, kb + (size_t)(s1 + row) * DD + c16 * 8);
                cpasync16(sb + vo + row * 144 + c16 * 16, vb + (size_t)(s1 + row) * DD + c16 * 8);
            }
            if (tid < 64) biasS[(buf ^ 1) * 64 + tid] = g_bias[b * LL + s1 + tid];
            CP_COMMIT();
            CP_WAIT1();
        } else {
            CP_WAIT0();
        }
        __syncthreads();

        if (ch == 0) {
#pragma unroll
            for (int kt = 0; kt < 4; kt++)
                ldsm4(aQ[kt], sb + (warp * 16 + (lane & 15)) * 144 + kt * 32 + (lane >> 4) * 16);
        }

        const uint32_t kOff = FOFF_K + buf * 9216;
        const uint32_t vOff = FOFF_V + buf * 9216;
        const float* bias_t = biasS + buf * 64;

        // ---- S = Q K^T (fp16)
        float S[8][4];
#pragma unroll
        for (int nt = 0; nt < 8; nt++)
#pragma unroll
            for (int c = 0; c < 4; c++) S[nt][c] = 0.0f;
#pragma unroll
        for (int ktp = 0; ktp < 2; ktp++) {
#pragma unroll
            for (int nt = 0; nt < 8; nt++) {
                uint32_t kB[4];
                ldsm4(kB, kOff + sb + (nt * 8 + (lane & 7)) * 144 + ktp * 64 + ((lane >> 3) & 3) * 16);
                mma_f16(S[nt], aQ[2 * ktp],     kB);
                mma_f16(S[nt], aQ[2 * ktp + 1], kB + 2);
            }
        }

        // ---- online softmax
        float rm0 = -1e30f, rm1 = -1e30f;
        float2 bv[8];
#pragma unroll
        for (int nt = 0; nt < 8; nt++) {
            bv[nt] = *(const float2*)&bias_t[nt * 8 + 2 * (lane & 3)];
            S[nt][0] = S[nt][0] * 0.125f + bv[nt].x;
            S[nt][1] = S[nt][1] * 0.125f + bv[nt].y;
            S[nt][2] = S[nt][2] * 0.125f + bv[nt].x;
            S[nt][3] = S[nt][3] * 0.125f + bv[nt].y;
            rm0 = fmaxf(rm0, fmaxf(S[nt][0], S[nt][1]));
            rm1 = fmaxf(rm1, fmaxf(S[nt][2], S[nt][3]));
        }
        rm0 = fmaxf(rm0, __shfl_xor_sync(0xffffffffu, rm0, 1));
        rm0 = fmaxf(rm0, __shfl_xor_sync(0xffffffffu, rm0, 2));
        rm1 = fmaxf(rm1, __shfl_xor_sync(0xffffffffu, rm1, 1));
        rm1 = fmaxf(rm1, __shfl_xor_sync(0xffffffffu, rm1, 2));
        float mn0 = fmaxf(m0, rm0), mn1 = fmaxf(m1, rm1);
        float sc0 = __expf(m0 - mn0), sc1 = __expf(m1 - mn1);
        m0 = mn0; m1 = mn1;

        uint32_t pe0[8], pe1[8];
        float rs0 = 0.0f, rs1 = 0.0f;
#pragma unroll
        for (int nt = 0; nt < 8; nt++) {
            __half2 e0 = h2exp(__floats2half2_rn(S[nt][0] - mn0, S[nt][1] - mn0));
            __half2 e1 = h2exp(__floats2half2_rn(S[nt][2] - mn1, S[nt][3] - mn1));
            pe0[nt] = *(uint32_t*)&e0;
            pe1[nt] = *(uint32_t*)&e1;
            float2 f0 = __half22float2(e0);
            float2 f1 = __half22float2(e1);
            rs0 += f0.x + f0.y;
            rs1 += f1.x + f1.y;
        }
        rs0 += __shfl_xor_sync(0xffffffffu, rs0, 1);
        rs0 += __shfl_xor_sync(0xffffffffu, rs0, 2);
        rs1 += __shfl_xor_sync(0xffffffffu, rs1, 1);
        rs1 += __shfl_xor_sync(0xffffffffu, rs1, 2);
        l0 = l0 * sc0 + rs0;
        l1 = l1 * sc1 + rs1;
#pragma unroll
        for (int nt = 0; nt < 8; nt++) {
            O[nt][0] *= sc0; O[nt][1] *= sc0;
            O[nt][2] *= sc1; O[nt][3] *= sc1;
        }

        // ---- O += P V  (P fragments = h2exp outputs, V via ldmatrix.trans)
#pragma unroll
        for (int kt = 0; kt < 4; kt++) {
            uint32_t aP[4] = { pe0[2*kt], pe1[2*kt], pe0[2*kt+1], pe1[2*kt+1] };
#pragma unroll
            for (int np = 0; np < 4; np++) {
                uint32_t vB[4];
                ldsm4t(vB, vOff + sb + (kt * 16 + (lane & 15)) * 144 + np * 32 + (lane >> 4) * 16);
                mma_f16(O[np * 2],     aP, vB);
                mma_f16(O[np * 2 + 1], aP, vB + 2);
            }
        }
        __syncthreads();
        buf ^= 1;
    }

    // ---- epilogue: normalize, write ctx as bf16 hi/lo
    const float il0 = 1.0f / l0, il1 = 1.0f / l1;
    const int row0 = q0 + warp * 16 + (lane >> 2);
    const size_t base0 = ((size_t)b * LL + row0) * CC + h * DD;
    const size_t base1 = base0 + (size_t)8 * CC;
#pragma unroll
    for (int nt = 0; nt < 8; nt++) {
        int col = nt * 8 + 2 * (lane & 3);
        {
            float o0 = O[nt][0] * il0, o1 = O[nt][1] * il0;
            __nv_bfloat16 h0 = __float2bfloat16_rn(o0);
            __nv_bfloat16 h1 = __float2bfloat16_rn(o1);
            __nv_bfloat162 hp; hp.x = h0; hp.y = h1;
            __nv_bfloat162 lp;
            lp.x = __float2bfloat16_rn(o0 - __bfloat162float(h0));
            lp.y = __float2bfloat16_rn(o1 - __bfloat162float(h1));
            *(__nv_bfloat162*)&g_chi[base0 + col] = hp;
            *(__nv_bfloat162*)&g_clo[base0 + col] = lp;
        }
        {
            float o0 = O[nt][2] * il1, o1 = O[nt][3] * il1;
            __nv_bfloat16 h0 = __float2bfloat16_rn(o0);
            __nv_bfloat16 h1 = __float2bfloat16_rn(o1);
            __nv_bfloat162 hp; hp.x = h0; hp.y = h1;
            __nv_bfloat162 lp;
            lp.x = __float2bfloat16_rn(o0 - __bfloat162float(h0));
            lp.y = __float2bfloat16_rn(o1 - __bfloat162float(h1));
            *(__nv_bfloat162*)&g_chi[base1 + col] = hp;
            *(__nv_bfloat162*)&g_clo[base1 + col] = lp;
        }
    }
}

// ---------------- launch -----------------------------------------------------
extern "C" void kernel_launch(void* const* d_in, const int* in_sizes, int n_in,
                              void* d_out, int out_size)
{
    const float* q  = (const float*)d_in[0];
    const void*  mk = d_in[1];
    const float* Wq = (const float*)d_in[2];
    const float* Wk = (const float*)d_in[3];
    const float* Wv = (const float*)d_in[4];
    const float* Wo = (const float*)d_in[5];
    const float* bo = (const float*)d_in[6];
    float* out = (float*)d_out;

    __nv_bfloat16 *xhi, *xlo, *whi, *wlo, *chi, *clo;
    cudaGetSymbolAddress((void**)&xhi, g_xhi);
    cudaGetSymbolAddress((void**)&xlo, g_xlo);
    cudaGetSymbolAddress((void**)&whi, g_whi);
    cudaGetSymbolAddress((void**)&wlo, g_wlo);
    cudaGetSymbolAddress((void**)&chi, g_chi);
    cudaGetSymbolAddress((void**)&clo, g_clo);

    cudaFuncSetAttribute(flash_kernel, cudaFuncAttributeMaxDynamicSharedMemorySize, FL_SMEM);
    cudaFuncSetAttribute(gemm_mma_kernel, cudaFuncAttributeMaxDynamicSharedMemorySize, GM_SMEM);

    detect_mask_kernel<<<1, 256>>>((const unsigned int*)mk);
    fill_bias_kernel<<<(BB*LL + 255) / 256, 256>>>(mk);
    rope_table_kernel<<<(LL*32 + 255) / 256, 256>>>();

    const int nx = ML * CC;
    const int nw = CC * CC;
    split_kernel<<<(nx/4 + 255) / 256, 256>>>(q,  xhi, xlo, nx);
    split_kernel<<<(nw/4 + 255) / 256, 256>>>(Wq, whi + 0*(size_t)nw, wlo + 0*(size_t)nw, nw);
    split_kernel<<<(nw/4 + 255) / 256, 256>>>(Wk, whi + 1*(size_t)nw, wlo + 1*(size_t)nw, nw);
    split_kernel<<<(nw/4 + 255) / 256, 256>>>(Wv, whi + 2*(size_t)nw, wlo + 2*(size_t)nw, nw);
    split_kernel<<<(nw/4 + 255) / 256, 256>>>(Wo, whi + 3*(size_t)nw, wlo + 3*(size_t)nw, nw);

    gemm_mma_kernel<<<dim3(CC/128, ML/128, 3), 256, GM_SMEM>>>(
        xhi, xlo, whi, wlo, nullptr, nullptr, 0);

    int ropeN = BB * HH * LL * 32;
    rope_apply_kernel<<<(ropeN + 255) / 256, 256>>>();

    flash_kernel<<<dim3(LL/128, BB*HH), 256, FL_SMEM>>>();

    gemm_mma_kernel<<<dim3(CC/128, ML/128, 1), 256, GM_SMEM>>>(
        chi, clo, whi + 3*(size_t)nw, wlo + 3*(size_t)nw, bo, out, 1);
}

// round 9
// speedup vs baseline: 4.6743x; 1.3119x over previous
#include <cuda_runtime.h>
#include <cuda_bf16.h>
#include <cuda_fp16.h>
#include <math.h>
#include <cstdint>

#define BB 2
#define LL 2048
#define CC 1024
#define HH 16
#define DD 64
#define ML (BB*LL)

// ---------------- MMA / ldmatrix helpers ------------------------------------
__device__ __forceinline__ uint32_t smem_u32(const void* p) {
    uint32_t a;
    asm("{ .reg .u64 t; cvta.to.shared.u64 t, %1; cvt.u32.u64 %0, t; }" : "=r"(a) : "l"(p));
    return a;
}
__device__ __forceinline__ void ldsm4(uint32_t* r, uint32_t addr) {
    asm volatile("ldmatrix.sync.aligned.m8n8.x4.shared.b16 {%0,%1,%2,%3}, [%4];"
        : "=r"(r[0]), "=r"(r[1]), "=r"(r[2]), "=r"(r[3]) : "r"(addr));
}
__device__ __forceinline__ void ldsm4t(uint32_t* r, uint32_t addr) {
    asm volatile("ldmatrix.sync.aligned.m8n8.x4.trans.shared.b16 {%0,%1,%2,%3}, [%4];"
        : "=r"(r[0]), "=r"(r[1]), "=r"(r[2]), "=r"(r[3]) : "r"(addr));
}
__device__ __forceinline__ void mma_f16(float* c, const uint32_t* a, const uint32_t* b) {
    asm volatile("mma.sync.aligned.m16n8k16.row.col.f32.f16.f16.f32 "
        "{%0,%1,%2,%3}, {%4,%5,%6,%7}, {%8,%9}, {%0,%1,%2,%3};"
        : "+f"(c[0]), "+f"(c[1]), "+f"(c[2]), "+f"(c[3])
        : "r"(a[0]), "r"(a[1]), "r"(a[2]), "r"(a[3]), "r"(b[0]), "r"(b[1]));
}
__device__ __forceinline__ void cpasync16(uint32_t saddr, const void* g) {
    asm volatile("cp.async.cg.shared.global [%0], [%1], 16;" :: "r"(saddr), "l"(g));
}
#define CP_COMMIT() asm volatile("cp.async.commit_group;" ::: "memory")
#define CP_WAIT1()  asm volatile("cp.async.wait_group 1;" ::: "memory")
#define CP_WAIT0()  asm volatile("cp.async.wait_group 0;" ::: "memory")

// ---------------- scratch ----------------------------------------------------
__device__ __half g_qhh[BB*HH*LL*DD];     // fp16 Q heads (RoPE applied in place)
__device__ __half g_khh[BB*HH*LL*DD];
__device__ __half g_vhh[BB*HH*LL*DD];
__device__ float  g_bias[BB*LL];
__device__ float2 g_ropeTab[LL*32];
__device__ int    g_maskfmt;
__device__ __half g_xhi[ML*CC], g_xlo[ML*CC];     // input split
__device__ __half g_w16[4*CC*CC];                 // Wq,Wk,Wv,Wo fp16
__device__ __half g_ctxhi[ML*CC], g_ctxlo[ML*CC]; // ctx split (from flash)

// ---------------- mask handling ---------------------------------------------
__global__ void detect_mask_kernel(const unsigned int* __restrict__ m) {
    __shared__ int s_i32, s_f32;
    if (threadIdx.x == 0) { s_i32 = 1; s_f32 = 1; }
    __syncthreads();
    int i32 = 1, f32 = 1;
    for (int i = threadIdx.x; i < 1024; i += 256) {
        unsigned v = m[i];
        if (v > 1u) i32 = 0;
        if (v != 0u && v != 0x3F800000u) f32 = 0;
    }
    if (!i32) atomicAnd(&s_i32, 0);
    if (!f32) atomicAnd(&s_f32, 0);
    __syncthreads();
    if (threadIdx.x == 0) g_maskfmt = s_i32 ? 0 : (s_f32 ? 1 : 2);
}

__global__ void fill_bias_kernel(const void* __restrict__ mp) {
    int i = blockIdx.x * 256 + threadIdx.x;
    if (i >= BB*LL) return;
    int fmt = g_maskfmt;
    bool on;
    if (fmt == 0)      on = ((const int*)mp)[i] != 0;
    else if (fmt == 1) on = ((const float*)mp)[i] != 0.0f;
    else               on = ((const unsigned char*)mp)[i] != 0;
    g_bias[i] = on ? 0.0f : -1e30f;
}

// ---------------- fp32 -> fp16 hi/lo split & convert ------------------------
__global__ void split16_kernel(const float* __restrict__ in, __half* __restrict__ hi,
                               __half* __restrict__ lo, int n) {
    int i = (blockIdx.x * 256 + threadIdx.x) * 4;
    if (i >= n) return;
    float4 v = *(const float4*)(in + i);
    __half h0 = __float2half_rn(v.x), h1 = __float2half_rn(v.y);
    __half h2 = __float2half_rn(v.z), h3 = __float2half_rn(v.w);
    __half l0 = __float2half_rn(v.x - __half2float(h0));
    __half l1 = __float2half_rn(v.y - __half2float(h1));
    __half l2 = __float2half_rn(v.z - __half2float(h2));
    __half l3 = __float2half_rn(v.w - __half2float(h3));
    __half2 hp0; hp0.x = h0; hp0.y = h1;
    __half2 hp1; hp1.x = h2; hp1.y = h3;
    __half2 lp0; lp0.x = l0; lp0.y = l1;
    __half2 lp1; lp1.x = l2; lp1.y = l3;
    *(__half2*)(hi + i)     = hp0;
    *(__half2*)(hi + i + 2) = hp1;
    *(__half2*)(lo + i)     = lp0;
    *(__half2*)(lo + i + 2) = lp1;
}

__global__ void cvt16_kernel(const float* __restrict__ in, __half* __restrict__ o16, int n) {
    int i = (blockIdx.x * 256 + threadIdx.x) * 4;
    if (i >= n) return;
    float4 v = *(const float4*)(in + i);
    __half2 p0 = __floats2half2_rn(v.x, v.y);
    __half2 p1 = __floats2half2_rn(v.z, v.w);
    *(__half2*)(o16 + i)     = p0;
    *(__half2*)(o16 + i + 2) = p1;
}

// ---------------- fp16 2-term HMMA NT GEMM ----------------------------------
// Block 128x128, 8 warps (warp tile 64x32), K-chunks 32, cp.async double-buffer.
// Per buffer: Ahi, Alo, W: 128 rows x 32 fp16, stride 80 B.
#define TILE_B   10240
#define BUF_B    (3*TILE_B)
#define GM_SMEM  (2*BUF_B)     /* 61440 */

__global__ __launch_bounds__(256)
void gemm_mma_kernel(const __half* __restrict__ Ahi, const __half* __restrict__ Alo,
                     const __half* __restrict__ Wall,
                     const float* __restrict__ bias, float* __restrict__ oout, int is_oproj)
{
    extern __shared__ __align__(128) char smem[];
    const uint32_t sb = smem_u32(smem);
    const int tid  = threadIdx.x;
    const int warp = tid >> 5;
    const int lane = tid & 31;
    const int bm = blockIdx.y * 128;
    const int bn = blockIdx.x * 128;
    const int z  = blockIdx.z;

    const __half* Wp = Wall + (size_t)z * CC * CC;

    // cp.async: 1536 tasks/chunk, 6 per thread; tile = j>>1 is compile-time.
#define LOAD_CHUNK(k0, bufbase)                                              \
    {                                                                        \
        _Pragma("unroll")                                                    \
        for (int j = 0; j < 6; j++) {                                        \
            const int tile = j >> 1;                                         \
            const int t = tid + (j & 1) * 256;                               \
            const int row = t >> 2, c16 = t & 3;                             \
            const __half* src = (tile == 0) ? Ahi : (tile == 1) ? Alo : Wp;  \
            const int baser = (tile < 2) ? bm : bn;                          \
            cpasync16((bufbase) + tile * TILE_B + row * 80 + c16 * 16,       \
                      src + (size_t)(baser + row) * CC + (k0) + c16 * 8);    \
        }                                                                    \
        CP_COMMIT();                                                         \
    }

    LOAD_CHUNK(0, sb)

    const int wm = (warp >> 2) * 64;
    const int wn = (warp & 3) * 32;
    uint32_t aoff[2][4][2];
#pragma unroll
    for (int dt = 0; dt < 2; dt++)
#pragma unroll
        for (int tm = 0; tm < 4; tm++)
#pragma unroll
            for (int ks = 0; ks < 2; ks++)
                aoff[dt][tm][ks] = sb + dt * TILE_B
                    + (wm + tm * 16 + (lane & 15)) * 80 + ks * 32 + (lane >> 4) * 16;
    uint32_t boff[4];
#pragma unroll
    for (int tn = 0; tn < 4; tn++)
        boff[tn] = sb + 2 * TILE_B
            + (wn + tn * 8 + (lane & 7)) * 80 + ((lane >> 3) & 3) * 16;

    float acc[4][4][4];
#pragma unroll
    for (int tm = 0; tm < 4; tm++)
#pragma unroll
        for (int tn = 0; tn < 4; tn++)
#pragma unroll
            for (int c = 0; c < 4; c++) acc[tm][tn][c] = 0.0f;

    int buf = 0;
    for (int ch = 0; ch < 32; ch++) {
        if (ch + 1 < 32) {
            LOAD_CHUNK((ch + 1) * 32, sb + (buf ^ 1) * BUF_B)
            CP_WAIT1();
        } else {
            CP_WAIT0();
        }
        __syncthreads();

        const uint32_t bo = buf * BUF_B;
        uint32_t bfrag[4][4];
#pragma unroll
        for (int tn = 0; tn < 4; tn++)
            ldsm4(bfrag[tn], boff[tn] + bo);
#pragma unroll
        for (int ks = 0; ks < 2; ks++) {
#pragma unroll
            for (int tm = 0; tm < 4; tm++) {
                uint32_t ah[4], al[4];
                ldsm4(ah, aoff[0][tm][ks] + bo);
                ldsm4(al, aoff[1][tm][ks] + bo);
#pragma unroll
                for (int tn = 0; tn < 4; tn++) {
                    mma_f16(acc[tm][tn], ah, &bfrag[tn][ks * 2]);
                    mma_f16(acc[tm][tn], al, &bfrag[tn][ks * 2]);
                }
            }
        }
        __syncthreads();
        buf ^= 1;
    }

    const int rbase = bm + wm + (lane >> 2);
    const int cbase = bn + wn + (lane & 3) * 2;
#pragma unroll
    for (int tm = 0; tm < 4; tm++) {
#pragma unroll
        for (int tn = 0; tn < 4; tn++) {
            int row0 = rbase + tm * 16;
            int col  = cbase + tn * 8;
            if (is_oproj) {
                float b0 = bias[col], b1 = bias[col + 1];
                *(float2*)&oout[(size_t)row0 * CC + col] =
                    make_float2(acc[tm][tn][0] + b0, acc[tm][tn][1] + b1);
                *(float2*)&oout[(size_t)(row0 + 8) * CC + col] =
                    make_float2(acc[tm][tn][2] + b0, acc[tm][tn][3] + b1);
            } else {
                __half* out = (z == 0) ? g_qhh : (z == 1) ? g_khh : g_vhh;
                const int h = col >> 6, d = col & 63;
                {
                    int b = row0 >> 11, l = row0 & (LL - 1);
                    *(__half2*)&out[(((size_t)b * HH + h) * LL + l) * DD + d] =
                        __floats2half2_rn(acc[tm][tn][0], acc[tm][tn][1]);
                }
                {
                    int r1 = row0 + 8;
                    int b = r1 >> 11, l = r1 & (LL - 1);
                    *(__half2*)&out[(((size_t)b * HH + h) * LL + l) * DD + d] =
                        __floats2half2_rn(acc[tm][tn][2], acc[tm][tn][3]);
                }
            }
        }
    }
}

// ---------------- RoPE ------------------------------------------------------
__global__ void rope_table_kernel() {
    int gid = blockIdx.x * 256 + threadIdx.x;
    if (gid >= LL*32) return;
    int d = gid & 31, l = gid >> 5;
    double inv = exp(-10.819778284410283 * (double)(2 * d) / 64.0);  // ln(50000)
    double sn, cs;
    sincos((double)l * inv, &sn, &cs);
    g_ropeTab[gid] = make_float2((float)cs, (float)sn);
}

// in-place fp16 rotation (each thread owns the (d, d+32) pair)
__global__ void rope_apply_kernel() {
    int gid = blockIdx.x * 256 + threadIdx.x;
    if (gid >= BB*HH*LL*32) return;
    int d   = gid & 31;
    int row = gid >> 5;
    int l   = row & (LL - 1);
    float2 cs = g_ropeTab[l * 32 + d];
    float c = cs.x, s = cs.y;
    __half* qp = g_qhh + (size_t)row * DD;
    __half* kp = g_khh + (size_t)row * DD;
    float a  = __half2float(qp[d]),  b2 = __half2float(qp[d + 32]);
    qp[d]      = __float2half_rn(a  * c - b2 * s);
    qp[d + 32] = __float2half_rn(b2 * c + a  * s);
    float ak = __half2float(kp[d]), bk = __half2float(kp[d + 32]);
    kp[d]      = __float2half_rn(ak * c - bk * s);
    kp[d + 32] = __float2half_rn(bk * c + ak * s);
}

// ---------------- Flash attention: fp16 HMMA + h2exp ------------------------
#define FOFF_K  18432
#define FOFF_V  36864
#define FOFF_BI 55296
#define FL_SMEM 55808

__global__ __launch_bounds__(256)
void flash_kernel()
{
    extern __shared__ __align__(128) char smx[];
    const uint32_t sb = smem_u32(smx);
    float* biasS = (float*)(smx + FOFF_BI);

    const int q0 = blockIdx.x * 128;
    const int bh = blockIdx.y;
    const int b  = bh >> 4;
    const int h  = bh & 15;
    const int tid  = threadIdx.x;
    const int warp = tid >> 5;
    const int lane = tid & 31;

    const __half* qb = g_qhh + (size_t)bh * LL * DD;
    const __half* kb = g_khh + (size_t)bh * LL * DD;
    const __half* vb = g_vhh + (size_t)bh * LL * DD;

    {
#pragma unroll
        for (int j = 0; j < 4; j++) {
            int t = tid + j * 256;
            int row = t >> 3, ch = t & 7;
            cpasync16(sb + row * 144 + ch * 16, qb + (size_t)(q0 + row) * DD + ch * 8);
        }
#pragma unroll
        for (int j = 0; j < 2; j++) {
            int t = tid + j * 256;
            int row = t >> 3, ch = t & 7;
            cpasync16(sb + FOFF_K + row * 144 + ch * 16, kb + (size_t)row * DD + ch * 8);
            cpasync16(sb + FOFF_V + row * 144 + ch * 16, vb + (size_t)row * DD + ch * 8);
        }
        if (tid < 64) biasS[tid] = g_bias[b * LL + tid];
        CP_COMMIT();
    }

    float O[8][4];
    float m0 = -1e30f, m1 = -1e30f, l0 = 0.0f, l1 = 0.0f;
#pragma unroll
    for (int nt = 0; nt < 8; nt++)
#pragma unroll
        for (int c = 0; c < 4; c++) O[nt][c] = 0.0f;

    uint32_t aQ[4][4];

    int buf = 0;
    for (int ch = 0; ch < 32; ch++) {
        if (ch + 1 < 32) {
            const int s1 = (ch + 1) * 64;
            const uint32_t ko = FOFF_K + (buf ^ 1) * 9216;
            const uint32_t vo = FOFF_V + (buf ^ 1) * 9216;
#pragma unroll
            for (int j = 0; j < 2; j++) {
                int t = tid + j * 256;
                int row = t >> 3, c16 = t & 7;
                cpasync16(sb + ko + row * 144 + c16 * 16, kb + (size_t)(s1 + row) * DD + c16 * 8);
                cpasync16(sb + vo + row * 144 + c16 * 16, vb + (size_t)(s1 + row) * DD + c16 * 8);
            }
            if (tid < 64) biasS[(buf ^ 1) * 64 + tid] = g_bias[b * LL + s1 + tid];
            CP_COMMIT();
            CP_WAIT1();
        } else {
            CP_WAIT0();
        }
        __syncthreads();

        if (ch == 0) {
#pragma unroll
            for (int kt = 0; kt < 4; kt++)
                ldsm4(aQ[kt], sb + (warp * 16 + (lane & 15)) * 144 + kt * 32 + (lane >> 4) * 16);
        }

        const uint32_t kOff = FOFF_K + buf * 9216;
        const uint32_t vOff = FOFF_V + buf * 9216;
        const float* bias_t = biasS + buf * 64;

        float S[8][4];
#pragma unroll
        for (int nt = 0; nt < 8; nt++)
#pragma unroll
            for (int c = 0; c < 4; c++) S[nt][c] = 0.0f;
#pragma unroll
        for (int ktp = 0; ktp < 2; ktp++) {
#pragma unroll
            for (int nt = 0; nt < 8; nt++) {
                uint32_t kB[4];
                ldsm4(kB, kOff + sb + (nt * 8 + (lane & 7)) * 144 + ktp * 64 + ((lane >> 3) & 3) * 16);
                mma_f16(S[nt], aQ[2 * ktp],     kB);
                mma_f16(S[nt], aQ[2 * ktp + 1], kB + 2);
            }
        }

        float rm0 = -1e30f, rm1 = -1e30f;
        float2 bv[8];
#pragma unroll
        for (int nt = 0; nt < 8; nt++) {
            bv[nt] = *(const float2*)&bias_t[nt * 8 + 2 * (lane & 3)];
            S[nt][0] = S[nt][0] * 0.125f + bv[nt].x;
            S[nt][1] = S[nt][1] * 0.125f + bv[nt].y;
            S[nt][2] = S[nt][2] * 0.125f + bv[nt].x;
            S[nt][3] = S[nt][3] * 0.125f + bv[nt].y;
            rm0 = fmaxf(rm0, fmaxf(S[nt][0], S[nt][1]));
            rm1 = fmaxf(rm1, fmaxf(S[nt][2], S[nt][3]));
        }
        rm0 = fmaxf(rm0, __shfl_xor_sync(0xffffffffu, rm0, 1));
        rm0 = fmaxf(rm0, __shfl_xor_sync(0xffffffffu, rm0, 2));
        rm1 = fmaxf(rm1, __shfl_xor_sync(0xffffffffu, rm1, 1));
        rm1 = fmaxf(rm1, __shfl_xor_sync(0xffffffffu, rm1, 2));
        float mn0 = fmaxf(m0, rm0), mn1 = fmaxf(m1, rm1);
        float sc0 = __expf(m0 - mn0), sc1 = __expf(m1 - mn1);
        m0 = mn0; m1 = mn1;

        uint32_t pe0[8], pe1[8];
        float rs0 = 0.0f, rs1 = 0.0f;
#pragma unroll
        for (int nt = 0; nt < 8; nt++) {
            __half2 e0 = h2exp(__floats2half2_rn(S[nt][0] - mn0, S[nt][1] - mn0));
            __half2 e1 = h2exp(__floats2half2_rn(S[nt][2] - mn1, S[nt][3] - mn1));
            pe0[nt] = *(uint32_t*)&e0;
            pe1[nt] = *(uint32_t*)&e1;
            float2 f0 = __half22float2(e0);
            float2 f1 = __half22float2(e1);
            rs0 += f0.x + f0.y;
            rs1 += f1.x + f1.y;
        }
        rs0 += __shfl_xor_sync(0xffffffffu, rs0, 1);
        rs0 += __shfl_xor_sync(0xffffffffu, rs0, 2);
        rs1 += __shfl_xor_sync(0xffffffffu, rs1, 1);
        rs1 += __shfl_xor_sync(0xffffffffu, rs1, 2);
        l0 = l0 * sc0 + rs0;
        l1 = l1 * sc1 + rs1;
#pragma unroll
        for (int nt = 0; nt < 8; nt++) {
            O[nt][0] *= sc0; O[nt][1] *= sc0;
            O[nt][2] *= sc1; O[nt][3] *= sc1;
        }

#pragma unroll
        for (int kt = 0; kt < 4; kt++) {
            uint32_t aP[4] = { pe0[2*kt], pe1[2*kt], pe0[2*kt+1], pe1[2*kt+1] };
#pragma unroll
            for (int np = 0; np < 4; np++) {
                uint32_t vB[4];
                ldsm4t(vB, vOff + sb + (kt * 16 + (lane & 15)) * 144 + np * 32 + (lane >> 4) * 16);
                mma_f16(O[np * 2],     aP, vB);
                mma_f16(O[np * 2 + 1], aP, vB + 2);
            }
        }
        __syncthreads();
        buf ^= 1;
    }

    // epilogue: normalize, write ctx as fp16 hi/lo
    const float il0 = 1.0f / l0, il1 = 1.0f / l1;
    const int row0 = q0 + warp * 16 + (lane >> 2);
    const size_t base0 = ((size_t)b * LL + row0) * CC + h * DD;
    const size_t base1 = base0 + (size_t)8 * CC;
#pragma unroll
    for (int nt = 0; nt < 8; nt++) {
        int col = nt * 8 + 2 * (lane & 3);
        {
            float o0 = O[nt][0] * il0, o1 = O[nt][1] * il0;
            __half h0 = __float2half_rn(o0), h1 = __float2half_rn(o1);
            __half2 hp; hp.x = h0; hp.y = h1;
            __half2 lp;
            lp.x = __float2half_rn(o0 - __half2float(h0));
            lp.y = __float2half_rn(o1 - __half2float(h1));
            *(__half2*)&g_ctxhi[base0 + col] = hp;
            *(__half2*)&g_ctxlo[base0 + col] = lp;
        }
        {
            float o0 = O[nt][2] * il1, o1 = O[nt][3] * il1;
            __half h0 = __float2half_rn(o0), h1 = __float2half_rn(o1);
            __half2 hp; hp.x = h0; hp.y = h1;
            __half2 lp;
            lp.x = __float2half_rn(o0 - __half2float(h0));
            lp.y = __float2half_rn(o1 - __half2float(h1));
            *(__half2*)&g_ctxhi[base1 + col] = hp;
            *(__half2*)&g_ctxlo[base1 + col] = lp;
        }
    }
}

// ---------------- launch -----------------------------------------------------
extern "C" void kernel_launch(void* const* d_in, const int* in_sizes, int n_in,
                              void* d_out, int out_size)
{
    const float* q  = (const float*)d_in[0];
    const void*  mk = d_in[1];
    const float* Wq = (const float*)d_in[2];
    const float* Wk = (const float*)d_in[3];
    const float* Wv = (const float*)d_in[4];
    const float* Wo = (const float*)d_in[5];
    const float* bo = (const float*)d_in[6];
    float* out = (float*)d_out;

    __half *xhi, *xlo, *w16, *chi, *clo;
    cudaGetSymbolAddress((void**)&xhi, g_xhi);
    cudaGetSymbolAddress((void**)&xlo, g_xlo);
    cudaGetSymbolAddress((void**)&w16, g_w16);
    cudaGetSymbolAddress((void**)&chi, g_ctxhi);
    cudaGetSymbolAddress((void**)&clo, g_ctxlo);

    cudaFuncSetAttribute(flash_kernel, cudaFuncAttributeMaxDynamicSharedMemorySize, FL_SMEM);
    cudaFuncSetAttribute(gemm_mma_kernel, cudaFuncAttributeMaxDynamicSharedMemorySize, GM_SMEM);

    detect_mask_kernel<<<1, 256>>>((const unsigned int*)mk);
    fill_bias_kernel<<<(BB*LL + 255) / 256, 256>>>(mk);
    rope_table_kernel<<<(LL*32 + 255) / 256, 256>>>();

    const int nx = ML * CC;
    const int nw = CC * CC;
    split16_kernel<<<(nx/4 + 255) / 256, 256>>>(q, xhi, xlo, nx);
    cvt16_kernel<<<(nw/4 + 255) / 256, 256>>>(Wq, w16 + 0*(size_t)nw, nw);
    cvt16_kernel<<<(nw/4 + 255) / 256, 256>>>(Wk, w16 + 1*(size_t)nw, nw);
    cvt16_kernel<<<(nw/4 + 255) / 256, 256>>>(Wv, w16 + 2*(size_t)nw, nw);
    cvt16_kernel<<<(nw/4 + 255) / 256, 256>>>(Wo, w16 + 3*(size_t)nw, nw);

    gemm_mma_kernel<<<dim3(CC/128, ML/128, 3), 256, GM_SMEM>>>(
        xhi, xlo, w16, nullptr, nullptr, 0);

    int ropeN = BB * HH * LL * 32;
    rope_apply_kernel<<<(ropeN + 255) / 256, 256>>>();

    flash_kernel<<<dim3(LL/128, BB*HH), 256, FL_SMEM>>>();

    gemm_mma_kernel<<<dim3(CC/128, ML/128, 1), 256, GM_SMEM>>>(
        chi, clo, w16 + 3*(size_t)nw, bo, out, 1);
}